// round 1
// baseline (speedup 1.0000x reference)
#include <cuda_runtime.h>
#include <cuda_bf16.h>
#include <math.h>
#include <stdint.h>

#define N_EMBD 1024
#define N_HEAD 16
#define HS 64
#define BATCH 4
#define SEQ 2048

// Scratch (allocation-free rule: __device__ globals)
__device__ float g_qkv[(size_t)BATCH * SEQ * 3 * N_EMBD]; // ~100.7 MB
__device__ float g_y[(size_t)BATCH * SEQ * N_EMBD];       // ~33.6 MB

// ---------------------------------------------------------------------------
// Classic fp32 SGEMM: C[M,N] = A[M,K] @ B[K,N], all row-major.
// 128x128 block tile, BK=8, 256 threads, 8x8 register tile per thread.
// Assumes M%128==0, N%128==0, K%8==0 (true for all shapes here).
// ---------------------------------------------------------------------------
__global__ __launch_bounds__(256) void sgemm128(
    const float* __restrict__ A, const float* __restrict__ B,
    float* __restrict__ C, int M, int N, int K)
{
    __shared__ float As[8][128];
    __shared__ float Bs[8][128];

    const int tid = threadIdx.x;
    const int tx = (tid & 15) * 8;   // col within 128
    const int ty = (tid >> 4) * 8;   // row within 128

    const float* Ab = A + (size_t)blockIdx.y * 128 * K;
    const float* Bb = B + (size_t)blockIdx.x * 128;
    float* Cb = C + (size_t)blockIdx.y * 128 * N + (size_t)blockIdx.x * 128;

    float acc[8][8];
    #pragma unroll
    for (int i = 0; i < 8; i++)
        #pragma unroll
        for (int j = 0; j < 8; j++) acc[i][j] = 0.f;

    const int arow = tid >> 1, acol = (tid & 1) * 4;   // A tile 128x8 as float4
    const int brow = tid >> 5, bcol = (tid & 31) * 4;  // B tile 8x128 as float4

    for (int k0 = 0; k0 < K; k0 += 8) {
        float4 a4 = *(const float4*)(Ab + (size_t)arow * K + k0 + acol);
        As[acol + 0][arow] = a4.x;
        As[acol + 1][arow] = a4.y;
        As[acol + 2][arow] = a4.z;
        As[acol + 3][arow] = a4.w;
        float4 b4 = *(const float4*)(Bb + (size_t)(k0 + brow) * N + bcol);
        *(float4*)&Bs[brow][bcol] = b4;
        __syncthreads();

        #pragma unroll
        for (int kk = 0; kk < 8; kk++) {
            float ar[8], br[8];
            #pragma unroll
            for (int i = 0; i < 8; i++) ar[i] = As[kk][ty + i];
            #pragma unroll
            for (int j = 0; j < 8; j++) br[j] = Bs[kk][tx + j];
            #pragma unroll
            for (int i = 0; i < 8; i++)
                #pragma unroll
                for (int j = 0; j < 8; j++)
                    acc[i][j] += ar[i] * br[j];
        }
        __syncthreads();
    }

    #pragma unroll
    for (int i = 0; i < 8; i++) {
        #pragma unroll
        for (int j = 0; j < 8; j += 4) {
            float4 v = make_float4(acc[i][j], acc[i][j + 1], acc[i][j + 2], acc[i][j + 3]);
            *(float4*)(Cb + (size_t)(ty + i) * N + tx + j) = v;
        }
    }
}

// ---------------------------------------------------------------------------
// fp32 flash attention (causal). qkv layout: [(b*SEQ+t), 3*N_EMBD] with
// q at col offset 0, k at N_EMBD, v at 2*N_EMBD; head h spans cols h*64..h*64+63.
// Block: 64 query rows x one (b,h). 256 threads: thread = (row = tid&63,
// cg = tid>>6) owning output dims [cg*16, cg*16+16).
// ---------------------------------------------------------------------------
__global__ __launch_bounds__(256) void flash_attn(
    const float* __restrict__ qkv, float* __restrict__ y)
{
    extern __shared__ float sm[];
    float (*Qs)[HS] = (float(*)[HS])sm;                    // 64x64
    float (*Ks)[HS] = (float(*)[HS])(sm + 64 * HS);        // 64x64
    float (*Vs)[HS] = (float(*)[HS])(sm + 2 * 64 * HS);    // 64x64
    float (*Ss)[64] = (float(*)[64])(sm + 3 * 64 * HS);    // 64x64 (P tile)
    float* redm = sm + 3 * 64 * HS + 64 * 64;              // [4][64]
    float* reds = redm + 4 * 64;                           // [4][64]

    const int qt = blockIdx.x;
    const int b = blockIdx.y / N_HEAD;
    const int h = blockIdx.y % N_HEAD;
    const int tid = threadIdx.x;
    const int row = tid & 63;
    const int cg = tid >> 6;
    const int C3 = 3 * N_EMBD;
    const int qg = qt * 64 + row;

    // Load Q tile
    const float* qptr = qkv + (size_t)(b * SEQ + qg) * C3 + h * HS;
    #pragma unroll
    for (int i = 0; i < 4; i++)
        *(float4*)&Qs[row][cg * 16 + i * 4] = *(const float4*)(qptr + cg * 16 + i * 4);

    float m = -1e30f, l = 0.f;
    float acc[16];
    #pragma unroll
    for (int i = 0; i < 16; i++) acc[i] = 0.f;
    const float scale = 0.125f;  // 1/sqrt(64)

    for (int j = 0; j <= qt; j++) {
        __syncthreads();  // protect K/V/Ss reuse from previous iteration
        const float* kptr = qkv + (size_t)(b * SEQ + j * 64 + row) * C3 + N_EMBD + h * HS;
        #pragma unroll
        for (int i = 0; i < 4; i++) {
            *(float4*)&Ks[row][cg * 16 + i * 4] = *(const float4*)(kptr + cg * 16 + i * 4);
            *(float4*)&Vs[row][cg * 16 + i * 4] = *(const float4*)(kptr + N_EMBD + cg * 16 + i * 4);
        }
        __syncthreads();

        // S[row][cg*16 .. cg*16+15] = Q[row] . K[key]
        float s[16];
        #pragma unroll
        for (int kk = 0; kk < 16; kk++) s[kk] = 0.f;
        #pragma unroll 4
        for (int k = 0; k < HS; k += 4) {
            float4 qv = *(const float4*)&Qs[row][k];
            #pragma unroll
            for (int kk = 0; kk < 16; kk++) {
                float4 kv = *(const float4*)&Ks[cg * 16 + kk][k];
                s[kk] += qv.x * kv.x + qv.y * kv.y + qv.z * kv.z + qv.w * kv.w;
            }
        }

        // Causal mask + scale + per-thread max
        const int kbase = j * 64 + cg * 16;
        float tmax = -1e30f;
        #pragma unroll
        for (int kk = 0; kk < 16; kk++) {
            s[kk] = (kbase + kk <= qg) ? s[kk] * scale : -1e30f;
            tmax = fmaxf(tmax, s[kk]);
        }
        redm[cg * 64 + row] = tmax;
        __syncthreads();
        float mnew = fmaxf(m, fmaxf(fmaxf(redm[row], redm[64 + row]),
                                    fmaxf(redm[128 + row], redm[192 + row])));

        float psum = 0.f;
        #pragma unroll
        for (int kk = 0; kk < 16; kk++) {
            float p = __expf(s[kk] - mnew);
            psum += p;
            Ss[row][cg * 16 + kk] = p;
        }
        reds[cg * 64 + row] = psum;
        __syncthreads();
        float tsum = reds[row] + reds[64 + row] + reds[128 + row] + reds[192 + row];
        float corr = __expf(m - mnew);
        l = l * corr + tsum;
        m = mnew;
        #pragma unroll
        for (int i = 0; i < 16; i++) acc[i] *= corr;

        // O[row][cg*16+i] += P[row][k] * V[k][cg*16+i]
        #pragma unroll 4
        for (int k = 0; k < 64; k++) {
            float pv = Ss[row][k];
            #pragma unroll
            for (int i = 0; i < 16; i += 4) {
                float4 vv = *(const float4*)&Vs[k][cg * 16 + i];
                acc[i]     += pv * vv.x;
                acc[i + 1] += pv * vv.y;
                acc[i + 2] += pv * vv.z;
                acc[i + 3] += pv * vv.w;
            }
        }
    }

    const float inv = 1.f / l;
    float* yptr = y + (size_t)(b * SEQ + qg) * N_EMBD + h * HS + cg * 16;
    #pragma unroll
    for (int i = 0; i < 16; i += 4) {
        float4 v = make_float4(acc[i] * inv, acc[i + 1] * inv,
                               acc[i + 2] * inv, acc[i + 3] * inv);
        *(float4*)(yptr + i) = v;
    }
}

// ---------------------------------------------------------------------------
// Launch: qkv GEMM -> flash attention -> proj GEMM
// ---------------------------------------------------------------------------
static const int FLASH_SMEM = (3 * 64 * HS + 64 * 64 + 8 * 64) * (int)sizeof(float); // 67584 B

extern "C" void kernel_launch(void* const* d_in, const int* in_sizes, int n_in,
                              void* d_out, int out_size)
{
    const float* x      = (const float*)d_in[0];
    const float* w_attn = (const float*)d_in[1];
    const float* w_proj = (const float*)d_in[2];
    float* out = (float*)d_out;

    float *qkv_p, *y_p;
    cudaGetSymbolAddress((void**)&qkv_p, g_qkv);
    cudaGetSymbolAddress((void**)&y_p, g_y);

    const int M = BATCH * SEQ;  // 8192

    // 1) qkv = x @ w_attn   [8192,1024] x [1024,3072]
    sgemm128<<<dim3(3 * N_EMBD / 128, M / 128), 256>>>(x, w_attn, qkv_p, M, 3 * N_EMBD, N_EMBD);

    // 2) flash attention -> y  [8192,1024]
    cudaFuncSetAttribute(flash_attn, cudaFuncAttributeMaxDynamicSharedMemorySize, FLASH_SMEM);
    flash_attn<<<dim3(SEQ / 64, BATCH * N_HEAD), 256, FLASH_SMEM>>>(qkv_p, y_p);

    // 3) out = y @ w_proj   [8192,1024] x [1024,1024]
    sgemm128<<<dim3(N_EMBD / 128, M / 128), 256>>>(y_p, w_proj, out, M, N_EMBD, N_EMBD);
}

// round 3
// speedup vs baseline: 1.3596x; 1.3596x over previous
#include <cuda_runtime.h>
#include <cuda_bf16.h>
#include <math.h>
#include <stdint.h>

#define N_EMBD 1024
#define N_HEAD 16
#define HS 64
#define BATCH 4
#define SEQ 2048
#define MTOT (BATCH * SEQ)

// Scratch (allocation-free rule: __device__ globals)
__device__ float g_qkv[(size_t)MTOT * 3 * N_EMBD];       // ~100.7 MB
__device__ float g_y[(size_t)MTOT * N_EMBD];             // ~33.6 MB
__device__ float g_wt_attn[(size_t)3 * N_EMBD * N_EMBD]; // w_attn^T  [3072,1024]
__device__ float g_wt_proj[(size_t)N_EMBD * N_EMBD];     // w_proj^T  [1024,1024]

// ---------------------------------------------------------------------------
// Helpers
// ---------------------------------------------------------------------------
__device__ __forceinline__ uint32_t f2tf32(float x) {
    uint32_t o;
    asm("cvt.rna.tf32.f32 %0, %1;" : "=r"(o) : "f"(x));
    return o;
}
__device__ __forceinline__ void cp_async16(uint32_t dst, const void* src) {
    asm volatile("cp.async.cg.shared.global [%0], [%1], 16;" :: "r"(dst), "l"(src));
}
#define CP_COMMIT() asm volatile("cp.async.commit_group;" ::: "memory")
#define CP_WAIT0() asm volatile("cp.async.wait_group 0;" ::: "memory")
#define CP_WAIT1() asm volatile("cp.async.wait_group 1;" ::: "memory")

__device__ __forceinline__ void mma_tf32(float* c, const uint32_t* a, const uint32_t* b) {
    asm volatile(
        "mma.sync.aligned.m16n8k8.row.col.f32.tf32.tf32.f32 "
        "{%0,%1,%2,%3}, {%4,%5,%6,%7}, {%8,%9}, {%0,%1,%2,%3};"
        : "+f"(c[0]), "+f"(c[1]), "+f"(c[2]), "+f"(c[3])
        : "r"(a[0]), "r"(a[1]), "r"(a[2]), "r"(a[3]), "r"(b[0]), "r"(b[1]));
}

// ---------------------------------------------------------------------------
// Transpose: out[n][k] = in[k][n]   (in: [R rows, C cols] row-major)
// ---------------------------------------------------------------------------
__global__ __launch_bounds__(256) void transpose_k(
    const float* __restrict__ in, float* __restrict__ out, int R, int C)
{
    __shared__ float t[32][33];
    const int bx = blockIdx.x * 32, by = blockIdx.y * 32;
    const int tx = threadIdx.x & 31, ty = threadIdx.x >> 5;
    #pragma unroll
    for (int i = ty; i < 32; i += 8)
        t[i][tx] = in[(size_t)(by + i) * C + bx + tx];
    __syncthreads();
    #pragma unroll
    for (int i = ty; i < 32; i += 8)
        out[(size_t)(bx + i) * R + by + tx] = t[tx][i];
}

// ---------------------------------------------------------------------------
// tf32 mma.sync GEMM: C[M,N] = A[M,K] @ Bt[N,K]^T
// 128x128 tile, BK=32, 256 threads (8 warps as 2x4, each 64x32),
// cp.async double-buffered smem. Requires M%128==0, N%128==0, K%32==0.
// smem: 2 buffers x (A 128x36 + B 128x36) floats = 73728 B.
// ---------------------------------------------------------------------------
#define BK 32
#define PADK 36
#define BUF_FLOATS (2 * 128 * PADK)          // per double-buffer slot (A+B)
#define GEMM_SMEM (2 * BUF_FLOATS * 4)       // 73728 B

__global__ __launch_bounds__(256, 2) void gemm_tf32(
    const float* __restrict__ A, const float* __restrict__ Bt,
    float* __restrict__ C, int M, int N, int K)
{
    extern __shared__ float sm[];
    const uint32_t sbase = (uint32_t)__cvta_generic_to_shared(sm);

    const int tid = threadIdx.x;
    const int wid = tid >> 5, lane = tid & 31;
    const int gr = lane >> 2, gc = lane & 3;
    const int wm = (wid & 1) * 64, wn = (wid >> 1) * 32;

    const float* Ag = A + (size_t)blockIdx.y * 128 * K;
    const float* Bg = Bt + (size_t)blockIdx.x * 128 * K;

    float acc[4][4][4];
    #pragma unroll
    for (int i = 0; i < 4; i++)
        #pragma unroll
        for (int j = 0; j < 4; j++)
            #pragma unroll
            for (int r = 0; r < 4; r++) acc[i][j][r] = 0.f;

    // each thread issues 4 A-quads + 4 B-quads per chunk
    const int NCH = K / BK;

    // prologue: chunk 0 into buffer 0
    {
        uint32_t aB = sbase;
        uint32_t bB = sbase + 128 * PADK * 4;
        #pragma unroll
        for (int i = 0; i < 4; i++) {
            int q = tid + 256 * i, r = q >> 3, qi = q & 7;
            cp_async16(aB + (uint32_t)(r * PADK + qi * 4) * 4, Ag + (size_t)r * K + qi * 4);
            cp_async16(bB + (uint32_t)(r * PADK + qi * 4) * 4, Bg + (size_t)r * K + qi * 4);
        }
        CP_COMMIT();
    }

    for (int c = 0; c < NCH; c++) {
        const int p = c & 1;
        if (c + 1 < NCH) {
            const int pn = p ^ 1, k0 = (c + 1) * BK;
            uint32_t aB = sbase + (uint32_t)pn * BUF_FLOATS * 4;
            uint32_t bB = aB + 128 * PADK * 4;
            #pragma unroll
            for (int i = 0; i < 4; i++) {
                int q = tid + 256 * i, r = q >> 3, qi = q & 7;
                cp_async16(aB + (uint32_t)(r * PADK + qi * 4) * 4, Ag + (size_t)r * K + k0 + qi * 4);
                cp_async16(bB + (uint32_t)(r * PADK + qi * 4) * 4, Bg + (size_t)r * K + k0 + qi * 4);
            }
            CP_COMMIT();
            CP_WAIT1();   // chunk c's group done; chunk c+1 may be in flight
        } else {
            CP_WAIT0();
        }
        __syncthreads();

        const float* As = sm + p * BUF_FLOATS;
        const float* Bs = As + 128 * PADK;

        #pragma unroll
        for (int ks = 0; ks < 4; ks++) {
            const int kc = ks * 8;
            uint32_t a[4][4], b[4][2];
            #pragma unroll
            for (int i = 0; i < 4; i++) {
                const float* ap = As + (wm + i * 16 + gr) * PADK + kc + gc;
                a[i][0] = f2tf32(ap[0]);
                a[i][1] = f2tf32(ap[8 * PADK]);
                a[i][2] = f2tf32(ap[4]);
                a[i][3] = f2tf32(ap[8 * PADK + 4]);
            }
            #pragma unroll
            for (int j = 0; j < 4; j++) {
                const float* bp = Bs + (wn + j * 8 + gr) * PADK + kc + gc;
                b[j][0] = f2tf32(bp[0]);
                b[j][1] = f2tf32(bp[4]);
            }
            #pragma unroll
            for (int i = 0; i < 4; i++)
                #pragma unroll
                for (int j = 0; j < 4; j++)
                    mma_tf32(acc[i][j], a[i], b[j]);
        }
        __syncthreads();   // buffer p reused by the prefetch two iterations out
    }

    // Epilogue
    float* Cg = C + (size_t)(blockIdx.y * 128 + wm) * N + blockIdx.x * 128 + wn;
    #pragma unroll
    for (int i = 0; i < 4; i++) {
        #pragma unroll
        for (int j = 0; j < 4; j++) {
            float2 v0 = make_float2(acc[i][j][0], acc[i][j][1]);
            float2 v1 = make_float2(acc[i][j][2], acc[i][j][3]);
            *(float2*)(Cg + (size_t)(i * 16 + gr) * N + j * 8 + gc * 2) = v0;
            *(float2*)(Cg + (size_t)(i * 16 + gr + 8) * N + j * 8 + gc * 2) = v1;
        }
    }
}

// ---------------------------------------------------------------------------
// fp32 flash attention (causal) — unchanged (known correct, Round-4 target).
// ---------------------------------------------------------------------------
__global__ __launch_bounds__(256) void flash_attn(
    const float* __restrict__ qkv, float* __restrict__ y)
{
    extern __shared__ float sm[];
    float (*Qs)[HS] = (float(*)[HS])sm;
    float (*Ks)[HS] = (float(*)[HS])(sm + 64 * HS);
    float (*Vs)[HS] = (float(*)[HS])(sm + 2 * 64 * HS);
    float (*Ss)[64] = (float(*)[64])(sm + 3 * 64 * HS);
    float* redm = sm + 3 * 64 * HS + 64 * 64;
    float* reds = redm + 4 * 64;

    const int qt = blockIdx.x;
    const int b = blockIdx.y / N_HEAD;
    const int h = blockIdx.y % N_HEAD;
    const int tid = threadIdx.x;
    const int row = tid & 63;
    const int cg = tid >> 6;
    const int C3 = 3 * N_EMBD;
    const int qg = qt * 64 + row;

    const float* qptr = qkv + (size_t)(b * SEQ + qg) * C3 + h * HS;
    #pragma unroll
    for (int i = 0; i < 4; i++)
        *(float4*)&Qs[row][cg * 16 + i * 4] = *(const float4*)(qptr + cg * 16 + i * 4);

    float m = -1e30f, l = 0.f;
    float acc[16];
    #pragma unroll
    for (int i = 0; i < 16; i++) acc[i] = 0.f;
    const float scale = 0.125f;

    for (int j = 0; j <= qt; j++) {
        __syncthreads();
        const float* kptr = qkv + (size_t)(b * SEQ + j * 64 + row) * C3 + N_EMBD + h * HS;
        #pragma unroll
        for (int i = 0; i < 4; i++) {
            *(float4*)&Ks[row][cg * 16 + i * 4] = *(const float4*)(kptr + cg * 16 + i * 4);
            *(float4*)&Vs[row][cg * 16 + i * 4] = *(const float4*)(kptr + N_EMBD + cg * 16 + i * 4);
        }
        __syncthreads();

        float s[16];
        #pragma unroll
        for (int kk = 0; kk < 16; kk++) s[kk] = 0.f;
        #pragma unroll 4
        for (int k = 0; k < HS; k += 4) {
            float4 qv = *(const float4*)&Qs[row][k];
            #pragma unroll
            for (int kk = 0; kk < 16; kk++) {
                float4 kv = *(const float4*)&Ks[cg * 16 + kk][k];
                s[kk] += qv.x * kv.x + qv.y * kv.y + qv.z * kv.z + qv.w * kv.w;
            }
        }

        const int kbase = j * 64 + cg * 16;
        float tmax = -1e30f;
        #pragma unroll
        for (int kk = 0; kk < 16; kk++) {
            s[kk] = (kbase + kk <= qg) ? s[kk] * scale : -1e30f;
            tmax = fmaxf(tmax, s[kk]);
        }
        redm[cg * 64 + row] = tmax;
        __syncthreads();
        float mnew = fmaxf(m, fmaxf(fmaxf(redm[row], redm[64 + row]),
                                    fmaxf(redm[128 + row], redm[192 + row])));

        float psum = 0.f;
        #pragma unroll
        for (int kk = 0; kk < 16; kk++) {
            float p = __expf(s[kk] - mnew);
            psum += p;
            Ss[row][cg * 16 + kk] = p;
        }
        reds[cg * 64 + row] = psum;
        __syncthreads();
        float tsum = reds[row] + reds[64 + row] + reds[128 + row] + reds[192 + row];
        float corr = __expf(m - mnew);
        l = l * corr + tsum;
        m = mnew;
        #pragma unroll
        for (int i = 0; i < 16; i++) acc[i] *= corr;

        #pragma unroll 4
        for (int k = 0; k < 64; k++) {
            float pv = Ss[row][k];
            #pragma unroll
            for (int i = 0; i < 16; i += 4) {
                float4 vv = *(const float4*)&Vs[k][cg * 16 + i];
                acc[i]     += pv * vv.x;
                acc[i + 1] += pv * vv.y;
                acc[i + 2] += pv * vv.z;
                acc[i + 3] += pv * vv.w;
            }
        }
    }

    const float inv = 1.f / l;
    float* yptr = y + (size_t)(b * SEQ + qg) * N_EMBD + h * HS + cg * 16;
    #pragma unroll
    for (int i = 0; i < 16; i += 4) {
        float4 v = make_float4(acc[i] * inv, acc[i + 1] * inv,
                               acc[i + 2] * inv, acc[i + 3] * inv);
        *(float4*)(yptr + i) = v;
    }
}

static const int FLASH_SMEM = (3 * 64 * HS + 64 * 64 + 8 * 64) * (int)sizeof(float);

extern "C" void kernel_launch(void* const* d_in, const int* in_sizes, int n_in,
                              void* d_out, int out_size)
{
    const float* x      = (const float*)d_in[0];
    const float* w_attn = (const float*)d_in[1];
    const float* w_proj = (const float*)d_in[2];
    float* out = (float*)d_out;

    float *qkv_p, *y_p, *wta, *wtp;
    cudaGetSymbolAddress((void**)&qkv_p, g_qkv);
    cudaGetSymbolAddress((void**)&y_p, g_y);
    cudaGetSymbolAddress((void**)&wta, g_wt_attn);
    cudaGetSymbolAddress((void**)&wtp, g_wt_proj);

    cudaFuncSetAttribute(gemm_tf32, cudaFuncAttributeMaxDynamicSharedMemorySize, GEMM_SMEM);
    cudaFuncSetAttribute(flash_attn, cudaFuncAttributeMaxDynamicSharedMemorySize, FLASH_SMEM);

    // 0) transpose weights: [K,N] -> [N,K]
    transpose_k<<<dim3(3 * N_EMBD / 32, N_EMBD / 32), 256>>>(w_attn, wta, N_EMBD, 3 * N_EMBD);
    transpose_k<<<dim3(N_EMBD / 32, N_EMBD / 32), 256>>>(w_proj, wtp, N_EMBD, N_EMBD);

    // 1) qkv = x @ w_attn   [8192,1024] x [1024,3072]
    gemm_tf32<<<dim3(3 * N_EMBD / 128, MTOT / 128), 256, GEMM_SMEM>>>(
        x, wta, qkv_p, MTOT, 3 * N_EMBD, N_EMBD);

    // 2) flash attention -> y
    flash_attn<<<dim3(SEQ / 64, BATCH * N_HEAD), 256, FLASH_SMEM>>>(qkv_p, y_p);

    // 3) out = y @ w_proj   [8192,1024] x [1024,1024]
    gemm_tf32<<<dim3(N_EMBD / 128, MTOT / 128), 256, GEMM_SMEM>>>(
        y_p, wtp, out, MTOT, N_EMBD, N_EMBD);
}

// round 4
// speedup vs baseline: 4.6254x; 3.4021x over previous
#include <cuda_runtime.h>
#include <cuda_bf16.h>
#include <math.h>
#include <stdint.h>

#define N_EMBD 1024
#define N_HEAD 16
#define HS 64
#define BATCH 4
#define SEQ 2048
#define MTOT (BATCH * SEQ)

// Scratch (allocation-free rule: __device__ globals)
__device__ float g_qkv[(size_t)MTOT * 3 * N_EMBD];
__device__ float g_y[(size_t)MTOT * N_EMBD];
__device__ float g_wt_attn[(size_t)3 * N_EMBD * N_EMBD];
__device__ float g_wt_proj[(size_t)N_EMBD * N_EMBD];

// ---------------------------------------------------------------------------
// Helpers
// ---------------------------------------------------------------------------
__device__ __forceinline__ uint32_t f2tf32(float x) {
    uint32_t o;
    asm("cvt.rna.tf32.f32 %0, %1;" : "=r"(o) : "f"(x));
    return o;
}
__device__ __forceinline__ void cp_async16(uint32_t dst, const void* src) {
    asm volatile("cp.async.cg.shared.global [%0], [%1], 16;" :: "r"(dst), "l"(src));
}
#define CP_COMMIT() asm volatile("cp.async.commit_group;" ::: "memory")
#define CP_WAIT0() asm volatile("cp.async.wait_group 0;" ::: "memory")
#define CP_WAIT1() asm volatile("cp.async.wait_group 1;" ::: "memory")

__device__ __forceinline__ void mma_tf32(float* c, const uint32_t* a, const uint32_t* b) {
    asm volatile(
        "mma.sync.aligned.m16n8k8.row.col.f32.tf32.tf32.f32 "
        "{%0,%1,%2,%3}, {%4,%5,%6,%7}, {%8,%9}, {%0,%1,%2,%3};"
        : "+f"(c[0]), "+f"(c[1]), "+f"(c[2]), "+f"(c[3])
        : "r"(a[0]), "r"(a[1]), "r"(a[2]), "r"(a[3]), "r"(b[0]), "r"(b[1]));
}

// ---------------------------------------------------------------------------
// Transpose: out[n][k] = in[k][n]
// ---------------------------------------------------------------------------
__global__ __launch_bounds__(256) void transpose_k(
    const float* __restrict__ in, float* __restrict__ out, int R, int C)
{
    __shared__ float t[32][33];
    const int bx = blockIdx.x * 32, by = blockIdx.y * 32;
    const int tx = threadIdx.x & 31, ty = threadIdx.x >> 5;
    #pragma unroll
    for (int i = ty; i < 32; i += 8)
        t[i][tx] = in[(size_t)(by + i) * C + bx + tx];
    __syncthreads();
    #pragma unroll
    for (int i = ty; i < 32; i += 8)
        out[(size_t)(bx + i) * R + by + tx] = t[tx][i];
}

// ---------------------------------------------------------------------------
// tf32 mma.sync GEMM (unchanged from R3, validated).
// ---------------------------------------------------------------------------
#define BK 32
#define PADK 36
#define BUF_FLOATS (2 * 128 * PADK)
#define GEMM_SMEM (2 * BUF_FLOATS * 4)

__global__ __launch_bounds__(256, 2) void gemm_tf32(
    const float* __restrict__ A, const float* __restrict__ Bt,
    float* __restrict__ C, int M, int N, int K)
{
    extern __shared__ float sm[];
    const uint32_t sbase = (uint32_t)__cvta_generic_to_shared(sm);

    const int tid = threadIdx.x;
    const int wid = tid >> 5, lane = tid & 31;
    const int gr = lane >> 2, gc = lane & 3;
    const int wm = (wid & 1) * 64, wn = (wid >> 1) * 32;

    const float* Ag = A + (size_t)blockIdx.y * 128 * K;
    const float* Bg = Bt + (size_t)blockIdx.x * 128 * K;

    float acc[4][4][4];
    #pragma unroll
    for (int i = 0; i < 4; i++)
        #pragma unroll
        for (int j = 0; j < 4; j++)
            #pragma unroll
            for (int r = 0; r < 4; r++) acc[i][j][r] = 0.f;

    const int NCH = K / BK;
    {
        uint32_t aB = sbase;
        uint32_t bB = sbase + 128 * PADK * 4;
        #pragma unroll
        for (int i = 0; i < 4; i++) {
            int q = tid + 256 * i, r = q >> 3, qi = q & 7;
            cp_async16(aB + (uint32_t)(r * PADK + qi * 4) * 4, Ag + (size_t)r * K + qi * 4);
            cp_async16(bB + (uint32_t)(r * PADK + qi * 4) * 4, Bg + (size_t)r * K + qi * 4);
        }
        CP_COMMIT();
    }

    for (int c = 0; c < NCH; c++) {
        const int p = c & 1;
        if (c + 1 < NCH) {
            const int pn = p ^ 1, k0 = (c + 1) * BK;
            uint32_t aB = sbase + (uint32_t)pn * BUF_FLOATS * 4;
            uint32_t bB = aB + 128 * PADK * 4;
            #pragma unroll
            for (int i = 0; i < 4; i++) {
                int q = tid + 256 * i, r = q >> 3, qi = q & 7;
                cp_async16(aB + (uint32_t)(r * PADK + qi * 4) * 4, Ag + (size_t)r * K + k0 + qi * 4);
                cp_async16(bB + (uint32_t)(r * PADK + qi * 4) * 4, Bg + (size_t)r * K + k0 + qi * 4);
            }
            CP_COMMIT();
            CP_WAIT1();
        } else {
            CP_WAIT0();
        }
        __syncthreads();

        const float* As = sm + p * BUF_FLOATS;
        const float* Bs = As + 128 * PADK;

        #pragma unroll
        for (int ks = 0; ks < 4; ks++) {
            const int kc = ks * 8;
            uint32_t a[4][4], b[4][2];
            #pragma unroll
            for (int i = 0; i < 4; i++) {
                const float* ap = As + (wm + i * 16 + gr) * PADK + kc + gc;
                a[i][0] = f2tf32(ap[0]);
                a[i][1] = f2tf32(ap[8 * PADK]);
                a[i][2] = f2tf32(ap[4]);
                a[i][3] = f2tf32(ap[8 * PADK + 4]);
            }
            #pragma unroll
            for (int j = 0; j < 4; j++) {
                const float* bp = Bs + (wn + j * 8 + gr) * PADK + kc + gc;
                b[j][0] = f2tf32(bp[0]);
                b[j][1] = f2tf32(bp[4]);
            }
            #pragma unroll
            for (int i = 0; i < 4; i++)
                #pragma unroll
                for (int j = 0; j < 4; j++)
                    mma_tf32(acc[i][j], a[i], b[j]);
        }
        __syncthreads();
    }

    float* Cg = C + (size_t)(blockIdx.y * 128 + wm) * N + blockIdx.x * 128 + wn;
    #pragma unroll
    for (int i = 0; i < 4; i++) {
        #pragma unroll
        for (int j = 0; j < 4; j++) {
            float2 v0 = make_float2(acc[i][j][0], acc[i][j][1]);
            float2 v1 = make_float2(acc[i][j][2], acc[i][j][3]);
            *(float2*)(Cg + (size_t)(i * 16 + gr) * N + j * 8 + gc * 2) = v0;
            *(float2*)(Cg + (size_t)(i * 16 + gr + 8) * N + j * 8 + gc * 2) = v1;
        }
    }
}

// ---------------------------------------------------------------------------
// tf32 mma.sync flash attention (causal).
// Q-tile 128, K-tile 64, 8 warps x 16 query rows. K double-buffered via
// cp.async; V register-transposed into XOR-swizzled Vt[hs][key] (tf32 bits);
// P roundtrips through smem (reusing the Q tile buffer; warp-private rows).
//
// smem floats: Ks[2][64*64] | Vt[2][64*64] | QP[128*68]
// ---------------------------------------------------------------------------
#define FPAD 68
#define KS_OFF 0
#define VT_OFF (2 * 64 * 64)
#define QP_OFF (4 * 64 * 64)
#define FLASH_SMEM ((4 * 64 * 64 + 128 * FPAD) * 4)   // 100352 B

__global__ __launch_bounds__(256, 2) void flash_attn_tf32(
    const float* __restrict__ qkv, float* __restrict__ y)
{
    extern __shared__ float sm[];
    const uint32_t sbase = (uint32_t)__cvta_generic_to_shared(sm);

    const int qt = gridDim.x - 1 - blockIdx.x;   // heavy tiles launch first
    const int bh = blockIdx.y;
    const int b = bh >> 4, h = bh & 15;
    const int tid = threadIdx.x, wid = tid >> 5, lane = tid & 31;
    const int gr = lane >> 2, gc = lane & 3;
    const int C3 = 3 * N_EMBD;
    const int q0 = qt * 128;
    const float* gb = qkv + (size_t)(b * SEQ) * C3 + h * HS;

    // ---- Q tile -> smem -> register fragments (held all kernel)
    #pragma unroll
    for (int i = 0; i < 8; i++) {
        int u = tid + 256 * i, r = u >> 4, q = u & 15;
        *(float4*)(sm + QP_OFF + r * FPAD + q * 4) =
            *(const float4*)(gb + (size_t)(q0 + r) * C3 + q * 4);
    }
    __syncthreads();
    uint32_t qa[8][4];
    {
        const float* Qw = sm + QP_OFF + (wid * 16) * FPAD;
        #pragma unroll
        for (int s = 0; s < 8; s++) {
            qa[s][0] = f2tf32(Qw[gr * FPAD + s * 8 + gc]);
            qa[s][1] = f2tf32(Qw[(gr + 8) * FPAD + s * 8 + gc]);
            qa[s][2] = f2tf32(Qw[gr * FPAD + s * 8 + gc + 4]);
            qa[s][3] = f2tf32(Qw[(gr + 8) * FPAD + s * 8 + gc + 4]);
        }
    }
    __syncthreads();   // QP now reusable as P

    const int r0 = q0 + wid * 16 + gr;
    const int r1 = r0 + 8;

    float o[8][4];
    #pragma unroll
    for (int t = 0; t < 8; t++)
        #pragma unroll
        for (int r = 0; r < 4; r++) o[t][r] = 0.f;
    float m0 = -1e30f, m1 = -1e30f, l0 = 0.f, l1 = 0.f;

    const int jmax = 2 * qt + 1;

    // V load coords: one 4x4 block per thread: bc = tid&15 (hs blk), br = tid>>4 (key blk)
    const int vbc = tid & 15, vbr = tid >> 4;
    // K cp.async coords: 4 quads per thread
    // prologue: K(0), V(0)
    {
        #pragma unroll
        for (int i = 0; i < 4; i++) {
            int u = tid + 256 * i, r = u >> 4, q = u & 15;
            uint32_t dst = sbase + (uint32_t)(KS_OFF + r * 64 + ((4 * q) ^ ((r & 7) << 2))) * 4;
            cp_async16(dst, gb + N_EMBD + (size_t)r * C3 + q * 4);
        }
        CP_COMMIT();
    }
    float4 vr[4];
    #pragma unroll
    for (int i = 0; i < 4; i++)
        vr[i] = *(const float4*)(gb + 2 * N_EMBD + (size_t)(4 * vbr + i) * C3 + 4 * vbc);

    for (int j = 0; j <= jmax; j++) {
        const int p = j & 1;
        // STS V(j) transposed + tf32-converted into Vt[p]
        {
            float* Vp = sm + VT_OFF + p * 64 * 64;
            const float vv[4][4] = {
                {vr[0].x, vr[0].y, vr[0].z, vr[0].w},
                {vr[1].x, vr[1].y, vr[1].z, vr[1].w},
                {vr[2].x, vr[2].y, vr[2].z, vr[2].w},
                {vr[3].x, vr[3].y, vr[3].z, vr[3].w}};
            #pragma unroll
            for (int k = 0; k < 4; k++) {
                int row = 4 * vbc + k;
                uint32_t col = (uint32_t)(4 * vbr) ^ (uint32_t)((row & 7) << 2);
                uint4 w = make_uint4(f2tf32(vv[0][k]), f2tf32(vv[1][k]),
                                     f2tf32(vv[2][k]), f2tf32(vv[3][k]));
                *(uint4*)(Vp + row * 64 + col) = w;
            }
        }
        const bool more = (j < jmax);
        if (more) {
            const int kb1 = (j + 1) * 64;
            #pragma unroll
            for (int i = 0; i < 4; i++) {
                int u = tid + 256 * i, r = u >> 4, q = u & 15;
                uint32_t dst = sbase + (uint32_t)(KS_OFF + (p ^ 1) * 64 * 64 +
                               r * 64 + ((4 * q) ^ ((r & 7) << 2))) * 4;
                cp_async16(dst, gb + N_EMBD + (size_t)(kb1 + r) * C3 + q * 4);
            }
            CP_COMMIT();
            #pragma unroll
            for (int i = 0; i < 4; i++)
                vr[i] = *(const float4*)(gb + 2 * N_EMBD +
                        (size_t)(kb1 + 4 * vbr + i) * C3 + 4 * vbc);
            CP_WAIT1();
        } else {
            CP_WAIT0();
        }
        __syncthreads();

        const int kb = j * 64;
        if (kb <= q0 + wid * 16 + 15) {  // warp not fully masked
            // ---- S = Q K^T
            float s[8][4];
            #pragma unroll
            for (int t = 0; t < 8; t++)
                #pragma unroll
                for (int r = 0; r < 4; r++) s[t][r] = 0.f;
            const float* Kp = sm + KS_OFF + p * 64 * 64;
            #pragma unroll
            for (int ks = 0; ks < 8; ks++) {
                #pragma unroll
                for (int t = 0; t < 8; t++) {
                    int n = 8 * t + gr;
                    uint32_t bb[2];
                    bb[0] = f2tf32(Kp[n * 64 + ((ks * 8 + gc) ^ ((n & 7) << 2))]);
                    bb[1] = f2tf32(Kp[n * 64 + ((ks * 8 + gc + 4) ^ ((n & 7) << 2))]);
                    mma_tf32(s[t], qa[ks], bb);
                }
            }
            // ---- mask + online softmax
            float tm0 = -1e30f, tm1 = -1e30f;
            #pragma unroll
            for (int t = 0; t < 8; t++) {
                const int c0 = kb + 8 * t + 2 * gc, c1 = c0 + 1;
                s[t][0] = (c0 <= r0) ? s[t][0] * 0.125f : -1e30f;
                s[t][1] = (c1 <= r0) ? s[t][1] * 0.125f : -1e30f;
                s[t][2] = (c0 <= r1) ? s[t][2] * 0.125f : -1e30f;
                s[t][3] = (c1 <= r1) ? s[t][3] * 0.125f : -1e30f;
                tm0 = fmaxf(tm0, fmaxf(s[t][0], s[t][1]));
                tm1 = fmaxf(tm1, fmaxf(s[t][2], s[t][3]));
            }
            #pragma unroll
            for (int off = 1; off <= 2; off <<= 1) {
                tm0 = fmaxf(tm0, __shfl_xor_sync(0xffffffffu, tm0, off));
                tm1 = fmaxf(tm1, __shfl_xor_sync(0xffffffffu, tm1, off));
            }
            const float m0n = fmaxf(m0, tm0), m1n = fmaxf(m1, tm1);
            float rs0 = 0.f, rs1 = 0.f;
            float* Pw = sm + QP_OFF + (wid * 16) * FPAD;
            #pragma unroll
            for (int t = 0; t < 8; t++) {
                float p0 = __expf(s[t][0] - m0n);
                float p1 = __expf(s[t][1] - m0n);
                float p2 = __expf(s[t][2] - m1n);
                float p3 = __expf(s[t][3] - m1n);
                rs0 += p0 + p1;
                rs1 += p2 + p3;
                *(float2*)(Pw + gr * FPAD + 8 * t + 2 * gc) = make_float2(p0, p1);
                *(float2*)(Pw + (gr + 8) * FPAD + 8 * t + 2 * gc) = make_float2(p2, p3);
            }
            #pragma unroll
            for (int off = 1; off <= 2; off <<= 1) {
                rs0 += __shfl_xor_sync(0xffffffffu, rs0, off);
                rs1 += __shfl_xor_sync(0xffffffffu, rs1, off);
            }
            const float c0f = __expf(m0 - m0n), c1f = __expf(m1 - m1n);
            l0 = l0 * c0f + rs0;
            l1 = l1 * c1f + rs1;
            m0 = m0n;
            m1 = m1n;
            #pragma unroll
            for (int t = 0; t < 8; t++) {
                o[t][0] *= c0f; o[t][1] *= c0f;
                o[t][2] *= c1f; o[t][3] *= c1f;
            }
            __syncwarp();
            // ---- O += P V   (A = P from smem, B = Vt swizzled tf32 bits)
            const float* Vp = sm + VT_OFF + p * 64 * 64;
            #pragma unroll
            for (int ks = 0; ks < 8; ks++) {
                uint32_t aa[4];
                aa[0] = f2tf32(Pw[gr * FPAD + ks * 8 + gc]);
                aa[1] = f2tf32(Pw[(gr + 8) * FPAD + ks * 8 + gc]);
                aa[2] = f2tf32(Pw[gr * FPAD + ks * 8 + gc + 4]);
                aa[3] = f2tf32(Pw[(gr + 8) * FPAD + ks * 8 + gc + 4]);
                #pragma unroll
                for (int t = 0; t < 8; t++) {
                    int n = 8 * t + gr;
                    uint32_t bb[2];
                    bb[0] = __float_as_uint(Vp[n * 64 + ((ks * 8 + gc) ^ ((n & 7) << 2))]);
                    bb[1] = __float_as_uint(Vp[n * 64 + ((ks * 8 + gc + 4) ^ ((n & 7) << 2))]);
                    mma_tf32(o[t], aa, bb);
                }
            }
        }
        __syncwarp();
    }

    // ---- epilogue
    const float i0 = 1.f / l0, i1 = 1.f / l1;
    float* y0 = y + (size_t)(b * SEQ + r0) * N_EMBD + h * HS;
    float* y1 = y + (size_t)(b * SEQ + r1) * N_EMBD + h * HS;
    #pragma unroll
    for (int t = 0; t < 8; t++) {
        *(float2*)(y0 + 8 * t + 2 * gc) = make_float2(o[t][0] * i0, o[t][1] * i0);
        *(float2*)(y1 + 8 * t + 2 * gc) = make_float2(o[t][2] * i1, o[t][3] * i1);
    }
}

extern "C" void kernel_launch(void* const* d_in, const int* in_sizes, int n_in,
                              void* d_out, int out_size)
{
    const float* x      = (const float*)d_in[0];
    const float* w_attn = (const float*)d_in[1];
    const float* w_proj = (const float*)d_in[2];
    float* out = (float*)d_out;

    float *qkv_p, *y_p, *wta, *wtp;
    cudaGetSymbolAddress((void**)&qkv_p, g_qkv);
    cudaGetSymbolAddress((void**)&y_p, g_y);
    cudaGetSymbolAddress((void**)&wta, g_wt_attn);
    cudaGetSymbolAddress((void**)&wtp, g_wt_proj);

    cudaFuncSetAttribute(gemm_tf32, cudaFuncAttributeMaxDynamicSharedMemorySize, GEMM_SMEM);
    cudaFuncSetAttribute(flash_attn_tf32, cudaFuncAttributeMaxDynamicSharedMemorySize, FLASH_SMEM);

    transpose_k<<<dim3(3 * N_EMBD / 32, N_EMBD / 32), 256>>>(w_attn, wta, N_EMBD, 3 * N_EMBD);
    transpose_k<<<dim3(N_EMBD / 32, N_EMBD / 32), 256>>>(w_proj, wtp, N_EMBD, N_EMBD);

    gemm_tf32<<<dim3(3 * N_EMBD / 128, MTOT / 128), 256, GEMM_SMEM>>>(
        x, wta, qkv_p, MTOT, 3 * N_EMBD, N_EMBD);

    flash_attn_tf32<<<dim3(SEQ / 128, BATCH * N_HEAD), 256, FLASH_SMEM>>>(qkv_p, y_p);

    gemm_tf32<<<dim3(N_EMBD / 128, MTOT / 128), 256, GEMM_SMEM>>>(
        y_p, wtp, out, MTOT, N_EMBD, N_EMBD);
}

// round 6
// speedup vs baseline: 12.6788x; 2.7411x over previous
// R6 = R5 resubmission: fp16 mma.sync pipeline (GEMMs + flash attention).
// R5 failed with "GB300 container failed twice" (infra, pre-execution);
// source audited for hangs/OOB — none found. Resubmitting unchanged to keep
// the experiment uncon-founded.
#include <cuda_runtime.h>
#include <cuda_fp16.h>
#include <math.h>
#include <stdint.h>

#define N_EMBD 1024
#define N_HEAD 16
#define HS 64
#define BATCH 4
#define SEQ 2048
#define MTOT (BATCH * SEQ)

// Scratch (allocation-free rule: __device__ globals)
__device__ __half g_xh[(size_t)MTOT * N_EMBD];
__device__ __half g_qkvh[(size_t)MTOT * 3 * N_EMBD];
__device__ __half g_yh[(size_t)MTOT * N_EMBD];
__device__ __half g_wta_h[(size_t)3 * N_EMBD * N_EMBD];
__device__ __half g_wtp_h[(size_t)N_EMBD * N_EMBD];

// ---------------------------------------------------------------------------
// Helpers
// ---------------------------------------------------------------------------
__device__ __forceinline__ void cp_async16(uint32_t dst, const void* src) {
    asm volatile("cp.async.cg.shared.global [%0], [%1], 16;" :: "r"(dst), "l"(src));
}
#define CP_COMMIT() asm volatile("cp.async.commit_group;" ::: "memory")
#define CP_WAIT0() asm volatile("cp.async.wait_group 0;" ::: "memory")
#define CP_WAIT1() asm volatile("cp.async.wait_group 1;" ::: "memory")

#define LDSM4(r0, r1, r2, r3, addr) \
    asm volatile("ldmatrix.sync.aligned.m8n8.x4.shared.b16 {%0,%1,%2,%3}, [%4];" \
                 : "=r"(r0), "=r"(r1), "=r"(r2), "=r"(r3) : "r"(addr))
#define LDSM4T(r0, r1, r2, r3, addr) \
    asm volatile("ldmatrix.sync.aligned.m8n8.x4.trans.shared.b16 {%0,%1,%2,%3}, [%4];" \
                 : "=r"(r0), "=r"(r1), "=r"(r2), "=r"(r3) : "r"(addr))

__device__ __forceinline__ void mma_f16(float* c, const uint32_t* a, const uint32_t* b) {
    asm volatile(
        "mma.sync.aligned.m16n8k16.row.col.f32.f16.f16.f32 "
        "{%0,%1,%2,%3}, {%4,%5,%6,%7}, {%8,%9}, {%0,%1,%2,%3};"
        : "+f"(c[0]), "+f"(c[1]), "+f"(c[2]), "+f"(c[3])
        : "r"(a[0]), "r"(a[1]), "r"(a[2]), "r"(a[3]), "r"(b[0]), "r"(b[1]));
}

__device__ __forceinline__ uint32_t pack_h2(float a, float b) {
    __half2 h = __floats2half2_rn(a, b);
    return *reinterpret_cast<uint32_t*>(&h);
}

// ---------------------------------------------------------------------------
// fp32 -> fp16 elementwise convert (vectorized)
// ---------------------------------------------------------------------------
__global__ __launch_bounds__(256) void cvt_half4(
    const float4* __restrict__ in, __half2* __restrict__ out, int n4)
{
    int i = blockIdx.x * blockDim.x + threadIdx.x;
    if (i < n4) {
        float4 v = in[i];
        out[2 * i] = __floats2half2_rn(v.x, v.y);
        out[2 * i + 1] = __floats2half2_rn(v.z, v.w);
    }
}

// ---------------------------------------------------------------------------
// Transpose + convert: out_h[n][k] = (half)in[k][n]
// ---------------------------------------------------------------------------
__global__ __launch_bounds__(256) void transpose_cvt(
    const float* __restrict__ in, __half* __restrict__ out, int R, int C)
{
    __shared__ float t[32][33];
    const int bx = blockIdx.x * 32, by = blockIdx.y * 32;
    const int tx = threadIdx.x & 31, ty = threadIdx.x >> 5;
    #pragma unroll
    for (int i = ty; i < 32; i += 8)
        t[i][tx] = in[(size_t)(by + i) * C + bx + tx];
    __syncthreads();
    #pragma unroll
    for (int i = ty; i < 32; i += 8)
        out[(size_t)(bx + i) * R + by + tx] = __float2half_rn(t[tx][i]);
}

// ---------------------------------------------------------------------------
// fp16 mma.sync GEMM: C[M,N] = A_h[M,K] @ Bt_h[N,K]^T, fp32 accumulate.
// 128x128 tile, BK=64, 8 warps (2x4, 64x32 each), cp.async double buffer,
// XOR-swizzled 16B units, ldmatrix fragment loads.
// smem: 2 buf x (A 16KB + B 16KB) = 65536 B.
// ---------------------------------------------------------------------------
#define GEMM_SMEM 65536

template <bool HALF_OUT>
__global__ __launch_bounds__(256, 2) void gemm_f16(
    const __half* __restrict__ A, const __half* __restrict__ Bt,
    void* __restrict__ Cv, int M, int N, int K)
{
    extern __shared__ char smc[];
    const uint32_t sb = (uint32_t)__cvta_generic_to_shared(smc);
    const int tid = threadIdx.x, wid = tid >> 5, lane = tid & 31;
    const int gr = lane >> 2, gc = lane & 3;
    const int g8 = lane >> 3, r8 = lane & 7;
    const int wm = (wid & 1) * 64, wn = (wid >> 1) * 32;

    const __half* Ag = A + (size_t)blockIdx.y * 128 * K;
    const __half* Bg = Bt + (size_t)blockIdx.x * 128 * K;

    float acc[4][4][4];
    #pragma unroll
    for (int i = 0; i < 4; i++)
        #pragma unroll
        for (int j = 0; j < 4; j++)
            #pragma unroll
            for (int r = 0; r < 4; r++) acc[i][j][r] = 0.f;

    auto issue = [&](int c) {
        const int p = c & 1, k0 = c * 64;
        const uint32_t aB = sb + p * 32768, bB = aB + 16384;
        #pragma unroll
        for (int i = 0; i < 4; i++) {
            int u = tid + 256 * i, r = u >> 3, cu = u & 7;
            uint32_t d = (uint32_t)(r * 128 + ((cu ^ (r & 7)) << 4));
            cp_async16(aB + d, Ag + (size_t)r * K + k0 + cu * 8);
            cp_async16(bB + d, Bg + (size_t)r * K + k0 + cu * 8);
        }
        CP_COMMIT();
    };

    issue(0);
    const int NCH = K / 64;
    for (int c = 0; c < NCH; c++) {
        const int p = c & 1;
        if (c + 1 < NCH) { issue(c + 1); CP_WAIT1(); } else { CP_WAIT0(); }
        __syncthreads();
        const uint32_t aB = sb + p * 32768, bB = aB + 16384;

        #pragma unroll
        for (int ks = 0; ks < 4; ks++) {
            uint32_t a[4][4], b[4][2];
            #pragma unroll
            for (int i = 0; i < 4; i++) {
                int row = wm + i * 16 + (g8 & 1) * 8 + r8;
                int unit = 2 * ks + (g8 >> 1);
                LDSM4(a[i][0], a[i][1], a[i][2], a[i][3],
                      aB + row * 128 + ((unit ^ (row & 7)) << 4));
            }
            #pragma unroll
            for (int jp = 0; jp < 2; jp++) {
                int row = wn + jp * 16 + (g8 >> 1) * 8 + r8;
                int unit = 2 * ks + (g8 & 1);
                LDSM4(b[2 * jp][0], b[2 * jp][1], b[2 * jp + 1][0], b[2 * jp + 1][1],
                      bB + row * 128 + ((unit ^ (row & 7)) << 4));
            }
            #pragma unroll
            for (int i = 0; i < 4; i++)
                #pragma unroll
                for (int j = 0; j < 4; j++)
                    mma_f16(acc[i][j], a[i], b[j]);
        }
        __syncthreads();   // all warps done reading buf p before it is refilled
    }

    if (HALF_OUT) {
        __half* Ch = (__half*)Cv + (size_t)(blockIdx.y * 128 + wm) * N + blockIdx.x * 128 + wn;
        #pragma unroll
        for (int i = 0; i < 4; i++)
            #pragma unroll
            for (int j = 0; j < 4; j++) {
                *(__half2*)(Ch + (size_t)(i * 16 + gr) * N + j * 8 + 2 * gc) =
                    __floats2half2_rn(acc[i][j][0], acc[i][j][1]);
                *(__half2*)(Ch + (size_t)(i * 16 + gr + 8) * N + j * 8 + 2 * gc) =
                    __floats2half2_rn(acc[i][j][2], acc[i][j][3]);
            }
    } else {
        float* Cf = (float*)Cv + (size_t)(blockIdx.y * 128 + wm) * N + blockIdx.x * 128 + wn;
        #pragma unroll
        for (int i = 0; i < 4; i++)
            #pragma unroll
            for (int j = 0; j < 4; j++) {
                *(float2*)(Cf + (size_t)(i * 16 + gr) * N + j * 8 + 2 * gc) =
                    make_float2(acc[i][j][0], acc[i][j][1]);
                *(float2*)(Cf + (size_t)(i * 16 + gr + 8) * N + j * 8 + 2 * gc) =
                    make_float2(acc[i][j][2], acc[i][j][3]);
            }
    }
}

// ---------------------------------------------------------------------------
// fp16 flash attention (causal). Q-tile 128, KV-tile 64, 8 warps x 16 rows.
// qkv stored fp16. K/V triple-buffered cp.async (race-free, 1 barrier/iter).
// ldmatrix for Q/K fragments, ldmatrix.trans for V (no manual transpose).
// P stays in registers (C-frag -> A-frag relayout). All accum fp32.
// smem: Q 16KB | K 3x8KB | V 3x8KB = 65536 B.
// ---------------------------------------------------------------------------
#define FQ_OFF 0
#define FK_OFF 16384
#define FV_OFF (16384 + 3 * 8192)
#define FLASH_SMEM 65536

__global__ __launch_bounds__(256, 2) void flash_f16(
    const __half* __restrict__ qkv, __half* __restrict__ y)
{
    extern __shared__ char smc[];
    const uint32_t sb = (uint32_t)__cvta_generic_to_shared(smc);
    const int qt = gridDim.x - 1 - blockIdx.x;   // heavy tiles first
    const int b = blockIdx.y >> 4, h = blockIdx.y & 15;
    const int tid = threadIdx.x, wid = tid >> 5, lane = tid & 31;
    const int gr = lane >> 2, gc = lane & 3;
    const int g8 = lane >> 3, r8 = lane & 7;
    const int C3 = 3 * N_EMBD;
    const int q0 = qt * 128;
    const __half* gb = qkv + (size_t)(b * SEQ) * C3 + h * HS;
    const int jmax = 2 * qt + 1;

    auto issue_kv = [&](int j) {
        const int p3 = j % 3, kb = j * 64;
        #pragma unroll
        for (int i = 0; i < 2; i++) {
            int u = tid + 256 * i, r = u >> 3, cu = u & 7;
            uint32_t d = (uint32_t)(r * 128 + ((cu ^ (r & 7)) << 4)) + p3 * 8192;
            cp_async16(sb + FK_OFF + d, gb + N_EMBD + (size_t)(kb + r) * C3 + cu * 8);
            cp_async16(sb + FV_OFF + d, gb + 2 * N_EMBD + (size_t)(kb + r) * C3 + cu * 8);
        }
        CP_COMMIT();
    };

    // prologue: group0 = Q + K(0) + V(0); group1 = K(1) + V(1)
    {
        #pragma unroll
        for (int i = 0; i < 4; i++) {
            int u = tid + 256 * i, r = u >> 3, cu = u & 7;
            cp_async16(sb + FQ_OFF + r * 128 + ((cu ^ (r & 7)) << 4),
                       gb + (size_t)(q0 + r) * C3 + cu * 8);
        }
        #pragma unroll
        for (int i = 0; i < 2; i++) {
            int u = tid + 256 * i, r = u >> 3, cu = u & 7;
            uint32_t d = (uint32_t)(r * 128 + ((cu ^ (r & 7)) << 4));
            cp_async16(sb + FK_OFF + d, gb + N_EMBD + (size_t)r * C3 + cu * 8);
            cp_async16(sb + FV_OFF + d, gb + 2 * N_EMBD + (size_t)r * C3 + cu * 8);
        }
        CP_COMMIT();
        issue_kv(1);
    }

    uint32_t qa[4][4];
    float o[8][4];
    #pragma unroll
    for (int t = 0; t < 8; t++)
        #pragma unroll
        for (int r = 0; r < 4; r++) o[t][r] = 0.f;
    float m0 = -1e30f, m1 = -1e30f, l0 = 0.f, l1 = 0.f;
    const int r0 = q0 + wid * 16 + gr, r1 = r0 + 8;

    for (int j = 0; j <= jmax; j++) {
        if (j == jmax) { CP_WAIT0(); } else { CP_WAIT1(); }
        __syncthreads();   // data(j) visible to all; all warps past compute(j-1)
        if (j + 2 <= jmax) issue_kv(j + 2);   // buf (j+2)%3 last read at compute(j-1)

        if (j == 0) {   // Q fragments (held in registers for the whole kernel)
            #pragma unroll
            for (int ks = 0; ks < 4; ks++) {
                int row = wid * 16 + (g8 & 1) * 8 + r8;
                int unit = 2 * ks + (g8 >> 1);
                LDSM4(qa[ks][0], qa[ks][1], qa[ks][2], qa[ks][3],
                      sb + FQ_OFF + row * 128 + ((unit ^ (row & 7)) << 4));
            }
        }

        const int p3 = j % 3, kb = j * 64;
        if (kb <= q0 + wid * 16 + 15) {   // warp not fully masked
            // ---- S = Q K^T
            const uint32_t Kb = sb + FK_OFF + p3 * 8192;
            float s[8][4];
            #pragma unroll
            for (int t = 0; t < 8; t++)
                #pragma unroll
                for (int r = 0; r < 4; r++) s[t][r] = 0.f;
            #pragma unroll
            for (int t = 0; t < 8; t++) {
                uint32_t bfr[8];
                #pragma unroll
                for (int kp = 0; kp < 2; kp++) {
                    int row = 8 * t + r8;
                    int unit = 4 * kp + g8;
                    LDSM4(bfr[4 * kp], bfr[4 * kp + 1], bfr[4 * kp + 2], bfr[4 * kp + 3],
                          Kb + row * 128 + ((unit ^ (row & 7)) << 4));
                }
                #pragma unroll
                for (int ks = 0; ks < 4; ks++)
                    mma_f16(s[t], qa[ks], &bfr[2 * ks]);
            }
            // ---- mask + online softmax
            float tm0 = -1e30f, tm1 = -1e30f;
            #pragma unroll
            for (int t = 0; t < 8; t++) {
                const int c0 = kb + 8 * t + 2 * gc, c1 = c0 + 1;
                s[t][0] = (c0 <= r0) ? s[t][0] * 0.125f : -1e30f;
                s[t][1] = (c1 <= r0) ? s[t][1] * 0.125f : -1e30f;
                s[t][2] = (c0 <= r1) ? s[t][2] * 0.125f : -1e30f;
                s[t][3] = (c1 <= r1) ? s[t][3] * 0.125f : -1e30f;
                tm0 = fmaxf(tm0, fmaxf(s[t][0], s[t][1]));
                tm1 = fmaxf(tm1, fmaxf(s[t][2], s[t][3]));
            }
            #pragma unroll
            for (int off = 1; off <= 2; off <<= 1) {
                tm0 = fmaxf(tm0, __shfl_xor_sync(0xffffffffu, tm0, off));
                tm1 = fmaxf(tm1, __shfl_xor_sync(0xffffffffu, tm1, off));
            }
            const float m0n = fmaxf(m0, tm0), m1n = fmaxf(m1, tm1);
            uint32_t pa[4][4];
            float rs0 = 0.f, rs1 = 0.f;
            #pragma unroll
            for (int t = 0; t < 8; t++) {
                float p0 = __expf(s[t][0] - m0n);
                float p1 = __expf(s[t][1] - m0n);
                float p2 = __expf(s[t][2] - m1n);
                float p3f = __expf(s[t][3] - m1n);
                rs0 += p0 + p1;
                rs1 += p2 + p3f;
                const int ks = t >> 1, hi = (t & 1) * 2;
                pa[ks][hi] = pack_h2(p0, p1);        // rows m,   kv pair
                pa[ks][hi + 1] = pack_h2(p2, p3f);   // rows m+8
            }
            #pragma unroll
            for (int off = 1; off <= 2; off <<= 1) {
                rs0 += __shfl_xor_sync(0xffffffffu, rs0, off);
                rs1 += __shfl_xor_sync(0xffffffffu, rs1, off);
            }
            const float c0f = __expf(m0 - m0n), c1f = __expf(m1 - m1n);
            l0 = l0 * c0f + rs0;
            l1 = l1 * c1f + rs1;
            m0 = m0n; m1 = m1n;
            #pragma unroll
            for (int t = 0; t < 8; t++) {
                o[t][0] *= c0f; o[t][1] *= c0f;
                o[t][2] *= c1f; o[t][3] *= c1f;
            }
            // ---- O += P V  (V^T fragments via ldmatrix.trans, P in registers)
            const uint32_t Vb = sb + FV_OFF + p3 * 8192;
            #pragma unroll
            for (int tp = 0; tp < 4; tp++) {
                #pragma unroll
                for (int ks = 0; ks < 4; ks++) {
                    uint32_t bv[4];
                    int row = 16 * ks + (g8 & 1) * 8 + r8;
                    int unit = 2 * tp + (g8 >> 1);
                    LDSM4T(bv[0], bv[1], bv[2], bv[3],
                           Vb + row * 128 + ((unit ^ (row & 7)) << 4));
                    mma_f16(o[2 * tp], pa[ks], &bv[0]);
                    mma_f16(o[2 * tp + 1], pa[ks], &bv[2]);
                }
            }
        }
    }

    // ---- epilogue (y stored fp16 for the proj GEMM)
    const float i0 = 1.f / l0, i1 = 1.f / l1;
    __half* y0 = y + (size_t)(b * SEQ + r0) * N_EMBD + h * HS;
    __half* y1 = y + (size_t)(b * SEQ + r1) * N_EMBD + h * HS;
    #pragma unroll
    for (int t = 0; t < 8; t++) {
        *(__half2*)(y0 + 8 * t + 2 * gc) = __floats2half2_rn(o[t][0] * i0, o[t][1] * i0);
        *(__half2*)(y1 + 8 * t + 2 * gc) = __floats2half2_rn(o[t][2] * i1, o[t][3] * i1);
    }
}

// ---------------------------------------------------------------------------
// Launch
// ---------------------------------------------------------------------------
extern "C" void kernel_launch(void* const* d_in, const int* in_sizes, int n_in,
                              void* d_out, int out_size)
{
    const float* x      = (const float*)d_in[0];
    const float* w_attn = (const float*)d_in[1];
    const float* w_proj = (const float*)d_in[2];
    float* out = (float*)d_out;

    __half *xh, *qkvh, *yh, *wta, *wtp;
    cudaGetSymbolAddress((void**)&xh, g_xh);
    cudaGetSymbolAddress((void**)&qkvh, g_qkvh);
    cudaGetSymbolAddress((void**)&yh, g_yh);
    cudaGetSymbolAddress((void**)&wta, g_wta_h);
    cudaGetSymbolAddress((void**)&wtp, g_wtp_h);

    cudaFuncSetAttribute(gemm_f16<true>, cudaFuncAttributeMaxDynamicSharedMemorySize, GEMM_SMEM);
    cudaFuncSetAttribute(gemm_f16<false>, cudaFuncAttributeMaxDynamicSharedMemorySize, GEMM_SMEM);
    cudaFuncSetAttribute(flash_f16, cudaFuncAttributeMaxDynamicSharedMemorySize, FLASH_SMEM);

    // 0) conversions
    const int n4 = MTOT * N_EMBD / 4;
    cvt_half4<<<n4 / 256, 256>>>((const float4*)x, (__half2*)xh, n4);
    transpose_cvt<<<dim3(3 * N_EMBD / 32, N_EMBD / 32), 256>>>(w_attn, wta, N_EMBD, 3 * N_EMBD);
    transpose_cvt<<<dim3(N_EMBD / 32, N_EMBD / 32), 256>>>(w_proj, wtp, N_EMBD, N_EMBD);

    // 1) qkv_h = x_h @ w_attn  (fp16 out)
    gemm_f16<true><<<dim3(3 * N_EMBD / 128, MTOT / 128), 256, GEMM_SMEM>>>(
        xh, wta, qkvh, MTOT, 3 * N_EMBD, N_EMBD);

    // 2) flash attention -> y_h (fp16)
    flash_f16<<<dim3(SEQ / 128, BATCH * N_HEAD), 256, FLASH_SMEM>>>(qkvh, yh);

    // 3) out = y_h @ w_proj  (fp32 out)
    gemm_f16<false><<<dim3(N_EMBD / 128, MTOT / 128), 256, GEMM_SMEM>>>(
        yh, wtp, out, MTOT, N_EMBD, N_EMBD);
}

// round 9
// speedup vs baseline: 12.8203x; 1.0112x over previous
// R7: GEMM 3-stage cp.async (1 barrier/chunk) + ks-pipelined ldmatrix;
// softmax scale folded into QKV epilogue; flash unmasked fast path.
#include <cuda_runtime.h>
#include <cuda_fp16.h>
#include <math.h>
#include <stdint.h>

#define N_EMBD 1024
#define N_HEAD 16
#define HS 64
#define BATCH 4
#define SEQ 2048
#define MTOT (BATCH * SEQ)

__device__ __half g_xh[(size_t)MTOT * N_EMBD];
__device__ __half g_qkvh[(size_t)MTOT * 3 * N_EMBD];
__device__ __half g_yh[(size_t)MTOT * N_EMBD];
__device__ __half g_wta_h[(size_t)3 * N_EMBD * N_EMBD];
__device__ __half g_wtp_h[(size_t)N_EMBD * N_EMBD];

// ---------------------------------------------------------------------------
__device__ __forceinline__ void cp_async16(uint32_t dst, const void* src) {
    asm volatile("cp.async.cg.shared.global [%0], [%1], 16;" :: "r"(dst), "l"(src));
}
#define CP_COMMIT() asm volatile("cp.async.commit_group;" ::: "memory")
#define CP_WAIT0() asm volatile("cp.async.wait_group 0;" ::: "memory")
#define CP_WAIT1() asm volatile("cp.async.wait_group 1;" ::: "memory")

#define LDSM4(r0, r1, r2, r3, addr) \
    asm volatile("ldmatrix.sync.aligned.m8n8.x4.shared.b16 {%0,%1,%2,%3}, [%4];" \
                 : "=r"(r0), "=r"(r1), "=r"(r2), "=r"(r3) : "r"(addr))
#define LDSM4T(r0, r1, r2, r3, addr) \
    asm volatile("ldmatrix.sync.aligned.m8n8.x4.trans.shared.b16 {%0,%1,%2,%3}, [%4];" \
                 : "=r"(r0), "=r"(r1), "=r"(r2), "=r"(r3) : "r"(addr))

__device__ __forceinline__ void mma_f16(float* c, const uint32_t* a, const uint32_t* b) {
    asm volatile(
        "mma.sync.aligned.m16n8k16.row.col.f32.f16.f16.f32 "
        "{%0,%1,%2,%3}, {%4,%5,%6,%7}, {%8,%9}, {%0,%1,%2,%3};"
        : "+f"(c[0]), "+f"(c[1]), "+f"(c[2]), "+f"(c[3])
        : "r"(a[0]), "r"(a[1]), "r"(a[2]), "r"(a[3]), "r"(b[0]), "r"(b[1]));
}

__device__ __forceinline__ uint32_t pack_h2(float a, float b) {
    __half2 h = __floats2half2_rn(a, b);
    return *reinterpret_cast<uint32_t*>(&h);
}

// ---------------------------------------------------------------------------
__global__ __launch_bounds__(256) void cvt_half4(
    const float4* __restrict__ in, __half2* __restrict__ out, int n4)
{
    int i = blockIdx.x * blockDim.x + threadIdx.x;
    if (i < n4) {
        float4 v = in[i];
        out[2 * i] = __floats2half2_rn(v.x, v.y);
        out[2 * i + 1] = __floats2half2_rn(v.z, v.w);
    }
}

__global__ __launch_bounds__(256) void transpose_cvt(
    const float* __restrict__ in, __half* __restrict__ out, int R, int C)
{
    __shared__ float t[32][33];
    const int bx = blockIdx.x * 32, by = blockIdx.y * 32;
    const int tx = threadIdx.x & 31, ty = threadIdx.x >> 5;
    #pragma unroll
    for (int i = ty; i < 32; i += 8)
        t[i][tx] = in[(size_t)(by + i) * C + bx + tx];
    __syncthreads();
    #pragma unroll
    for (int i = ty; i < 32; i += 8)
        out[(size_t)(bx + i) * R + by + tx] = __float2half_rn(t[tx][i]);
}

// ---------------------------------------------------------------------------
// fp16 GEMM, 128x128 tile, BK=64, 3-stage cp.async (1 barrier/chunk),
// ks-pipelined ldmatrix fragments. scaleQ: multiply cols<1024 by 0.125
// (exact in fp16; pre-folds the attention softmax scale into q).
// smem: 3 x 32KB = 98304 B.
// ---------------------------------------------------------------------------
#define GEMM_SMEM (3 * 32768)

template <bool HALF_OUT>
__global__ __launch_bounds__(256, 2) void gemm_f16(
    const __half* __restrict__ A, const __half* __restrict__ Bt,
    void* __restrict__ Cv, int M, int N, int K, int scaleQ)
{
    extern __shared__ char smc[];
    const uint32_t sb = (uint32_t)__cvta_generic_to_shared(smc);
    const int tid = threadIdx.x, wid = tid >> 5, lane = tid & 31;
    const int gr = lane >> 2, gc = lane & 3;
    const int g8 = lane >> 3, r8 = lane & 7;
    const int wm = (wid & 1) * 64, wn = (wid >> 1) * 32;

    const __half* Ag = A + (size_t)blockIdx.y * 128 * K;
    const __half* Bg = Bt + (size_t)blockIdx.x * 128 * K;

    float acc[4][4][4];
    #pragma unroll
    for (int i = 0; i < 4; i++)
        #pragma unroll
        for (int j = 0; j < 4; j++)
            #pragma unroll
            for (int r = 0; r < 4; r++) acc[i][j][r] = 0.f;

    auto issue = [&](int c) {
        const int p3 = c % 3, k0 = c * 64;
        const uint32_t aB = sb + p3 * 32768, bB = aB + 16384;
        #pragma unroll
        for (int i = 0; i < 4; i++) {
            int u = tid + 256 * i, r = u >> 3, cu = u & 7;
            uint32_t d = (uint32_t)(r * 128 + ((cu ^ (r & 7)) << 4));
            cp_async16(aB + d, Ag + (size_t)r * K + k0 + cu * 8);
            cp_async16(bB + d, Bg + (size_t)r * K + k0 + cu * 8);
        }
        CP_COMMIT();
    };

    const int NCH = K / 64;
    issue(0);
    issue(1);
    for (int c = 0; c < NCH; c++) {
        if (c + 1 < NCH) { CP_WAIT1(); } else { CP_WAIT0(); }
        __syncthreads();   // data(c) visible; all warps past compute(c-1)
        if (c + 2 < NCH) issue(c + 2);   // buf (c+2)%3 last read at compute(c-1)

        const int p3 = c % 3;
        const uint32_t aB = sb + p3 * 32768, bB = aB + 16384;

        uint32_t a[2][4][4], b[2][4][2];
        auto ldfrag = [&](int ks, int pb) {
            #pragma unroll
            for (int i = 0; i < 4; i++) {
                int row = wm + i * 16 + (g8 & 1) * 8 + r8;
                int unit = 2 * ks + (g8 >> 1);
                LDSM4(a[pb][i][0], a[pb][i][1], a[pb][i][2], a[pb][i][3],
                      aB + row * 128 + ((unit ^ (row & 7)) << 4));
            }
            #pragma unroll
            for (int jp = 0; jp < 2; jp++) {
                int row = wn + jp * 16 + (g8 >> 1) * 8 + r8;
                int unit = 2 * ks + (g8 & 1);
                LDSM4(b[pb][2 * jp][0], b[pb][2 * jp][1],
                      b[pb][2 * jp + 1][0], b[pb][2 * jp + 1][1],
                      bB + row * 128 + ((unit ^ (row & 7)) << 4));
            }
        };
        ldfrag(0, 0);
        #pragma unroll
        for (int ks = 0; ks < 4; ks++) {
            if (ks < 3) ldfrag(ks + 1, (ks + 1) & 1);   // LDSM(ks+1) under MMA(ks)
            const int pb = ks & 1;
            #pragma unroll
            for (int i = 0; i < 4; i++)
                #pragma unroll
                for (int j = 0; j < 4; j++)
                    mma_f16(acc[i][j], a[pb][i], b[pb][j]);
        }
        // no trailing barrier: next iteration's sync orders buffer reuse
    }

    const float sc = (scaleQ && blockIdx.x < 8) ? 0.125f : 1.0f;
    if (HALF_OUT) {
        __half* Ch = (__half*)Cv + (size_t)(blockIdx.y * 128 + wm) * N + blockIdx.x * 128 + wn;
        #pragma unroll
        for (int i = 0; i < 4; i++)
            #pragma unroll
            for (int j = 0; j < 4; j++) {
                *(__half2*)(Ch + (size_t)(i * 16 + gr) * N + j * 8 + 2 * gc) =
                    __floats2half2_rn(acc[i][j][0] * sc, acc[i][j][1] * sc);
                *(__half2*)(Ch + (size_t)(i * 16 + gr + 8) * N + j * 8 + 2 * gc) =
                    __floats2half2_rn(acc[i][j][2] * sc, acc[i][j][3] * sc);
            }
    } else {
        float* Cf = (float*)Cv + (size_t)(blockIdx.y * 128 + wm) * N + blockIdx.x * 128 + wn;
        #pragma unroll
        for (int i = 0; i < 4; i++)
            #pragma unroll
            for (int j = 0; j < 4; j++) {
                *(float2*)(Cf + (size_t)(i * 16 + gr) * N + j * 8 + 2 * gc) =
                    make_float2(acc[i][j][0], acc[i][j][1]);
                *(float2*)(Cf + (size_t)(i * 16 + gr + 8) * N + j * 8 + 2 * gc) =
                    make_float2(acc[i][j][2], acc[i][j][3]);
            }
    }
}

// ---------------------------------------------------------------------------
// fp16 flash attention (causal). Q pre-scaled by 1/8 in the QKV GEMM.
// Q-tile 128, KV-tile 64, 8 warps x 16 rows, triple-buffered cp.async,
// ldmatrix / ldmatrix.trans, P in registers. Unmasked fast path.
// smem: Q 16KB | K 3x8KB | V 3x8KB = 65536 B.
// ---------------------------------------------------------------------------
#define FQ_OFF 0
#define FK_OFF 16384
#define FV_OFF (16384 + 3 * 8192)
#define FLASH_SMEM 65536

__global__ __launch_bounds__(256, 2) void flash_f16(
    const __half* __restrict__ qkv, __half* __restrict__ y)
{
    extern __shared__ char smc[];
    const uint32_t sb = (uint32_t)__cvta_generic_to_shared(smc);
    const int qt = gridDim.x - 1 - blockIdx.x;   // heavy tiles first
    const int b = blockIdx.y >> 4, h = blockIdx.y & 15;
    const int tid = threadIdx.x, wid = tid >> 5, lane = tid & 31;
    const int gr = lane >> 2, gc = lane & 3;
    const int g8 = lane >> 3, r8 = lane & 7;
    const int C3 = 3 * N_EMBD;
    const int q0 = qt * 128;
    const __half* gb = qkv + (size_t)(b * SEQ) * C3 + h * HS;
    const int jmax = 2 * qt + 1;

    auto issue_kv = [&](int j) {
        const int p3 = j % 3, kb = j * 64;
        #pragma unroll
        for (int i = 0; i < 2; i++) {
            int u = tid + 256 * i, r = u >> 3, cu = u & 7;
            uint32_t d = (uint32_t)(r * 128 + ((cu ^ (r & 7)) << 4)) + p3 * 8192;
            cp_async16(sb + FK_OFF + d, gb + N_EMBD + (size_t)(kb + r) * C3 + cu * 8);
            cp_async16(sb + FV_OFF + d, gb + 2 * N_EMBD + (size_t)(kb + r) * C3 + cu * 8);
        }
        CP_COMMIT();
    };

    {
        #pragma unroll
        for (int i = 0; i < 4; i++) {
            int u = tid + 256 * i, r = u >> 3, cu = u & 7;
            cp_async16(sb + FQ_OFF + r * 128 + ((cu ^ (r & 7)) << 4),
                       gb + (size_t)(q0 + r) * C3 + cu * 8);
        }
        #pragma unroll
        for (int i = 0; i < 2; i++) {
            int u = tid + 256 * i, r = u >> 3, cu = u & 7;
            uint32_t d = (uint32_t)(r * 128 + ((cu ^ (r & 7)) << 4));
            cp_async16(sb + FK_OFF + d, gb + N_EMBD + (size_t)r * C3 + cu * 8);
            cp_async16(sb + FV_OFF + d, gb + 2 * N_EMBD + (size_t)r * C3 + cu * 8);
        }
        CP_COMMIT();
        issue_kv(1);
    }

    uint32_t qa[4][4];
    float o[8][4];
    #pragma unroll
    for (int t = 0; t < 8; t++)
        #pragma unroll
        for (int r = 0; r < 4; r++) o[t][r] = 0.f;
    float m0 = -1e30f, m1 = -1e30f, l0 = 0.f, l1 = 0.f;
    const int r0 = q0 + wid * 16 + gr, r1 = r0 + 8;

    for (int j = 0; j <= jmax; j++) {
        if (j == jmax) { CP_WAIT0(); } else { CP_WAIT1(); }
        __syncthreads();
        if (j + 2 <= jmax) issue_kv(j + 2);

        if (j == 0) {
            #pragma unroll
            for (int ks = 0; ks < 4; ks++) {
                int row = wid * 16 + (g8 & 1) * 8 + r8;
                int unit = 2 * ks + (g8 >> 1);
                LDSM4(qa[ks][0], qa[ks][1], qa[ks][2], qa[ks][3],
                      sb + FQ_OFF + row * 128 + ((unit ^ (row & 7)) << 4));
            }
        }

        const int p3 = j % 3, kb = j * 64;
        if (kb <= q0 + wid * 16 + 15) {   // warp not fully masked
            const uint32_t Kb = sb + FK_OFF + p3 * 8192;
            float s[8][4];
            #pragma unroll
            for (int t = 0; t < 8; t++)
                #pragma unroll
                for (int r = 0; r < 4; r++) s[t][r] = 0.f;
            #pragma unroll
            for (int t = 0; t < 8; t++) {
                uint32_t bfr[8];
                #pragma unroll
                for (int kp = 0; kp < 2; kp++) {
                    int row = 8 * t + r8;
                    int unit = 4 * kp + g8;
                    LDSM4(bfr[4 * kp], bfr[4 * kp + 1], bfr[4 * kp + 2], bfr[4 * kp + 3],
                          Kb + row * 128 + ((unit ^ (row & 7)) << 4));
                }
                #pragma unroll
                for (int ks = 0; ks < 4; ks++)
                    mma_f16(s[t], qa[ks], &bfr[2 * ks]);
            }
            // ---- mask (only near diagonal) + online softmax; Q pre-scaled.
            float tm0 = -1e30f, tm1 = -1e30f;
            if (kb + 63 < q0 + wid * 16) {   // warp-uniform: fully unmasked
                #pragma unroll
                for (int t = 0; t < 8; t++) {
                    tm0 = fmaxf(tm0, fmaxf(s[t][0], s[t][1]));
                    tm1 = fmaxf(tm1, fmaxf(s[t][2], s[t][3]));
                }
            } else {
                #pragma unroll
                for (int t = 0; t < 8; t++) {
                    const int c0 = kb + 8 * t + 2 * gc, c1 = c0 + 1;
                    s[t][0] = (c0 <= r0) ? s[t][0] : -1e30f;
                    s[t][1] = (c1 <= r0) ? s[t][1] : -1e30f;
                    s[t][2] = (c0 <= r1) ? s[t][2] : -1e30f;
                    s[t][3] = (c1 <= r1) ? s[t][3] : -1e30f;
                    tm0 = fmaxf(tm0, fmaxf(s[t][0], s[t][1]));
                    tm1 = fmaxf(tm1, fmaxf(s[t][2], s[t][3]));
                }
            }
            #pragma unroll
            for (int off = 1; off <= 2; off <<= 1) {
                tm0 = fmaxf(tm0, __shfl_xor_sync(0xffffffffu, tm0, off));
                tm1 = fmaxf(tm1, __shfl_xor_sync(0xffffffffu, tm1, off));
            }
            const float m0n = fmaxf(m0, tm0), m1n = fmaxf(m1, tm1);
            uint32_t pa[4][4];
            float rs0 = 0.f, rs1 = 0.f;
            #pragma unroll
            for (int t = 0; t < 8; t++) {
                float p0 = __expf(s[t][0] - m0n);
                float p1 = __expf(s[t][1] - m0n);
                float p2 = __expf(s[t][2] - m1n);
                float p3f = __expf(s[t][3] - m1n);
                rs0 += p0 + p1;
                rs1 += p2 + p3f;
                const int ks = t >> 1, hi = (t & 1) * 2;
                pa[ks][hi] = pack_h2(p0, p1);
                pa[ks][hi + 1] = pack_h2(p2, p3f);
            }
            #pragma unroll
            for (int off = 1; off <= 2; off <<= 1) {
                rs0 += __shfl_xor_sync(0xffffffffu, rs0, off);
                rs1 += __shfl_xor_sync(0xffffffffu, rs1, off);
            }
            const float c0f = __expf(m0 - m0n), c1f = __expf(m1 - m1n);
            l0 = l0 * c0f + rs0;
            l1 = l1 * c1f + rs1;
            m0 = m0n; m1 = m1n;
            #pragma unroll
            for (int t = 0; t < 8; t++) {
                o[t][0] *= c0f; o[t][1] *= c0f;
                o[t][2] *= c1f; o[t][3] *= c1f;
            }
            const uint32_t Vb = sb + FV_OFF + p3 * 8192;
            #pragma unroll
            for (int tp = 0; tp < 4; tp++) {
                #pragma unroll
                for (int ks = 0; ks < 4; ks++) {
                    uint32_t bv[4];
                    int row = 16 * ks + (g8 & 1) * 8 + r8;
                    int unit = 2 * tp + (g8 >> 1);
                    LDSM4T(bv[0], bv[1], bv[2], bv[3],
                           Vb + row * 128 + ((unit ^ (row & 7)) << 4));
                    mma_f16(o[2 * tp], pa[ks], &bv[0]);
                    mma_f16(o[2 * tp + 1], pa[ks], &bv[2]);
                }
            }
        }
    }

    const float i0 = 1.f / l0, i1 = 1.f / l1;
    __half* y0 = y + (size_t)(b * SEQ + r0) * N_EMBD + h * HS;
    __half* y1 = y + (size_t)(b * SEQ + r1) * N_EMBD + h * HS;
    #pragma unroll
    for (int t = 0; t < 8; t++) {
        *(__half2*)(y0 + 8 * t + 2 * gc) = __floats2half2_rn(o[t][0] * i0, o[t][1] * i0);
        *(__half2*)(y1 + 8 * t + 2 * gc) = __floats2half2_rn(o[t][2] * i1, o[t][3] * i1);
    }
}

// ---------------------------------------------------------------------------
extern "C" void kernel_launch(void* const* d_in, const int* in_sizes, int n_in,
                              void* d_out, int out_size)
{
    const float* x      = (const float*)d_in[0];
    const float* w_attn = (const float*)d_in[1];
    const float* w_proj = (const float*)d_in[2];
    float* out = (float*)d_out;

    __half *xh, *qkvh, *yh, *wta, *wtp;
    cudaGetSymbolAddress((void**)&xh, g_xh);
    cudaGetSymbolAddress((void**)&qkvh, g_qkvh);
    cudaGetSymbolAddress((void**)&yh, g_yh);
    cudaGetSymbolAddress((void**)&wta, g_wta_h);
    cudaGetSymbolAddress((void**)&wtp, g_wtp_h);

    cudaFuncSetAttribute(gemm_f16<true>, cudaFuncAttributeMaxDynamicSharedMemorySize, GEMM_SMEM);
    cudaFuncSetAttribute(gemm_f16<false>, cudaFuncAttributeMaxDynamicSharedMemorySize, GEMM_SMEM);
    cudaFuncSetAttribute(flash_f16, cudaFuncAttributeMaxDynamicSharedMemorySize, FLASH_SMEM);

    const int n4 = MTOT * N_EMBD / 4;
    cvt_half4<<<n4 / 256, 256>>>((const float4*)x, (__half2*)xh, n4);
    transpose_cvt<<<dim3(3 * N_EMBD / 32, N_EMBD / 32), 256>>>(w_attn, wta, N_EMBD, 3 * N_EMBD);
    transpose_cvt<<<dim3(N_EMBD / 32, N_EMBD / 32), 256>>>(w_proj, wtp, N_EMBD, N_EMBD);

    // qkv = x @ w_attn, with q columns pre-scaled by 0.125
    gemm_f16<true><<<dim3(3 * N_EMBD / 128, MTOT / 128), 256, GEMM_SMEM>>>(
        xh, wta, qkvh, MTOT, 3 * N_EMBD, N_EMBD, 1);

    flash_f16<<<dim3(SEQ / 128, BATCH * N_HEAD), 256, FLASH_SMEM>>>(qkvh, yh);

    gemm_f16<false><<<dim3(N_EMBD / 128, MTOT / 128), 256, GEMM_SMEM>>>(
        yh, wtp, out, MTOT, N_EMBD, N_EMBD, 0);
}

// round 13
// speedup vs baseline: 13.2008x; 1.0297x over previous
// R10: GEMM reverted to R6 2-stage structure (measured faster than R9 3-stage);
// Q pre-scale now 0.125*log2(e) so flash softmax runs in raw ex2 domain.
#include <cuda_runtime.h>
#include <cuda_fp16.h>
#include <math.h>
#include <stdint.h>

#define N_EMBD 1024
#define N_HEAD 16
#define HS 64
#define BATCH 4
#define SEQ 2048
#define MTOT (BATCH * SEQ)

__device__ __half g_xh[(size_t)MTOT * N_EMBD];
__device__ __half g_qkvh[(size_t)MTOT * 3 * N_EMBD];
__device__ __half g_yh[(size_t)MTOT * N_EMBD];
__device__ __half g_wta_h[(size_t)3 * N_EMBD * N_EMBD];
__device__ __half g_wtp_h[(size_t)N_EMBD * N_EMBD];

// ---------------------------------------------------------------------------
__device__ __forceinline__ void cp_async16(uint32_t dst, const void* src) {
    asm volatile("cp.async.cg.shared.global [%0], [%1], 16;" :: "r"(dst), "l"(src));
}
#define CP_COMMIT() asm volatile("cp.async.commit_group;" ::: "memory")
#define CP_WAIT0() asm volatile("cp.async.wait_group 0;" ::: "memory")
#define CP_WAIT1() asm volatile("cp.async.wait_group 1;" ::: "memory")

#define LDSM4(r0, r1, r2, r3, addr) \
    asm volatile("ldmatrix.sync.aligned.m8n8.x4.shared.b16 {%0,%1,%2,%3}, [%4];" \
                 : "=r"(r0), "=r"(r1), "=r"(r2), "=r"(r3) : "r"(addr))
#define LDSM4T(r0, r1, r2, r3, addr) \
    asm volatile("ldmatrix.sync.aligned.m8n8.x4.trans.shared.b16 {%0,%1,%2,%3}, [%4];" \
                 : "=r"(r0), "=r"(r1), "=r"(r2), "=r"(r3) : "r"(addr))

__device__ __forceinline__ void mma_f16(float* c, const uint32_t* a, const uint32_t* b) {
    asm volatile(
        "mma.sync.aligned.m16n8k16.row.col.f32.f16.f16.f32 "
        "{%0,%1,%2,%3}, {%4,%5,%6,%7}, {%8,%9}, {%0,%1,%2,%3};"
        : "+f"(c[0]), "+f"(c[1]), "+f"(c[2]), "+f"(c[3])
        : "r"(a[0]), "r"(a[1]), "r"(a[2]), "r"(a[3]), "r"(b[0]), "r"(b[1]));
}

__device__ __forceinline__ uint32_t pack_h2(float a, float b) {
    __half2 h = __floats2half2_rn(a, b);
    return *reinterpret_cast<uint32_t*>(&h);
}
__device__ __forceinline__ float ex2f(float x) {
    float r;
    asm("ex2.approx.f32 %0, %1;" : "=f"(r) : "f"(x));
    return r;
}

// ---------------------------------------------------------------------------
__global__ __launch_bounds__(256) void cvt_half4(
    const float4* __restrict__ in, __half2* __restrict__ out, int n4)
{
    int i = blockIdx.x * blockDim.x + threadIdx.x;
    if (i < n4) {
        float4 v = in[i];
        out[2 * i] = __floats2half2_rn(v.x, v.y);
        out[2 * i + 1] = __floats2half2_rn(v.z, v.w);
    }
}

__global__ __launch_bounds__(256) void transpose_cvt(
    const float* __restrict__ in, __half* __restrict__ out, int R, int C)
{
    __shared__ float t[32][33];
    const int bx = blockIdx.x * 32, by = blockIdx.y * 32;
    const int tx = threadIdx.x & 31, ty = threadIdx.x >> 5;
    #pragma unroll
    for (int i = ty; i < 32; i += 8)
        t[i][tx] = in[(size_t)(by + i) * C + bx + tx];
    __syncthreads();
    #pragma unroll
    for (int i = ty; i < 32; i += 8)
        out[(size_t)(bx + i) * R + by + tx] = __float2half_rn(t[tx][i]);
}

// ---------------------------------------------------------------------------
// fp16 GEMM (R6 structure: 2-stage cp.async, simple inner loop).
// scaleQ: q columns (blockIdx.x<8) scaled by 0.125*log2(e) in epilogue.
// ---------------------------------------------------------------------------
#define GEMM_SMEM 65536
#define QSCALE (0.125f * 1.4426950408889634f)

template <bool HALF_OUT>
__global__ __launch_bounds__(256, 2) void gemm_f16(
    const __half* __restrict__ A, const __half* __restrict__ Bt,
    void* __restrict__ Cv, int M, int N, int K, int scaleQ)
{
    extern __shared__ char smc[];
    const uint32_t sb = (uint32_t)__cvta_generic_to_shared(smc);
    const int tid = threadIdx.x, wid = tid >> 5, lane = tid & 31;
    const int gr = lane >> 2, gc = lane & 3;
    const int g8 = lane >> 3, r8 = lane & 7;
    const int wm = (wid & 1) * 64, wn = (wid >> 1) * 32;

    const __half* Ag = A + (size_t)blockIdx.y * 128 * K;
    const __half* Bg = Bt + (size_t)blockIdx.x * 128 * K;

    float acc[4][4][4];
    #pragma unroll
    for (int i = 0; i < 4; i++)
        #pragma unroll
        for (int j = 0; j < 4; j++)
            #pragma unroll
            for (int r = 0; r < 4; r++) acc[i][j][r] = 0.f;

    auto issue = [&](int c) {
        const int p = c & 1, k0 = c * 64;
        const uint32_t aB = sb + p * 32768, bB = aB + 16384;
        #pragma unroll
        for (int i = 0; i < 4; i++) {
            int u = tid + 256 * i, r = u >> 3, cu = u & 7;
            uint32_t d = (uint32_t)(r * 128 + ((cu ^ (r & 7)) << 4));
            cp_async16(aB + d, Ag + (size_t)r * K + k0 + cu * 8);
            cp_async16(bB + d, Bg + (size_t)r * K + k0 + cu * 8);
        }
        CP_COMMIT();
    };

    issue(0);
    const int NCH = K / 64;
    for (int c = 0; c < NCH; c++) {
        const int p = c & 1;
        if (c + 1 < NCH) { issue(c + 1); CP_WAIT1(); } else { CP_WAIT0(); }
        __syncthreads();
        const uint32_t aB = sb + p * 32768, bB = aB + 16384;

        #pragma unroll
        for (int ks = 0; ks < 4; ks++) {
            uint32_t a[4][4], b[4][2];
            #pragma unroll
            for (int i = 0; i < 4; i++) {
                int row = wm + i * 16 + (g8 & 1) * 8 + r8;
                int unit = 2 * ks + (g8 >> 1);
                LDSM4(a[i][0], a[i][1], a[i][2], a[i][3],
                      aB + row * 128 + ((unit ^ (row & 7)) << 4));
            }
            #pragma unroll
            for (int jp = 0; jp < 2; jp++) {
                int row = wn + jp * 16 + (g8 >> 1) * 8 + r8;
                int unit = 2 * ks + (g8 & 1);
                LDSM4(b[2 * jp][0], b[2 * jp][1], b[2 * jp + 1][0], b[2 * jp + 1][1],
                      bB + row * 128 + ((unit ^ (row & 7)) << 4));
            }
            #pragma unroll
            for (int i = 0; i < 4; i++)
                #pragma unroll
                for (int j = 0; j < 4; j++)
                    mma_f16(acc[i][j], a[i], b[j]);
        }
        __syncthreads();
    }

    const float sc = (scaleQ && blockIdx.x < 8) ? QSCALE : 1.0f;
    if (HALF_OUT) {
        __half* Ch = (__half*)Cv + (size_t)(blockIdx.y * 128 + wm) * N + blockIdx.x * 128 + wn;
        #pragma unroll
        for (int i = 0; i < 4; i++)
            #pragma unroll
            for (int j = 0; j < 4; j++) {
                *(__half2*)(Ch + (size_t)(i * 16 + gr) * N + j * 8 + 2 * gc) =
                    __floats2half2_rn(acc[i][j][0] * sc, acc[i][j][1] * sc);
                *(__half2*)(Ch + (size_t)(i * 16 + gr + 8) * N + j * 8 + 2 * gc) =
                    __floats2half2_rn(acc[i][j][2] * sc, acc[i][j][3] * sc);
            }
    } else {
        float* Cf = (float*)Cv + (size_t)(blockIdx.y * 128 + wm) * N + blockIdx.x * 128 + wn;
        #pragma unroll
        for (int i = 0; i < 4; i++)
            #pragma unroll
            for (int j = 0; j < 4; j++) {
                *(float2*)(Cf + (size_t)(i * 16 + gr) * N + j * 8 + 2 * gc) =
                    make_float2(acc[i][j][0], acc[i][j][1]);
                *(float2*)(Cf + (size_t)(i * 16 + gr + 8) * N + j * 8 + 2 * gc) =
                    make_float2(acc[i][j][2], acc[i][j][3]);
            }
    }
}

// ---------------------------------------------------------------------------
// fp16 flash attention (causal), softmax in exp2 domain (Q pre-scaled by
// 0.125*log2e in the QKV GEMM, so p = ex2(s - m) directly).
// ---------------------------------------------------------------------------
#define FQ_OFF 0
#define FK_OFF 16384
#define FV_OFF (16384 + 3 * 8192)
#define FLASH_SMEM 65536

__global__ __launch_bounds__(256, 2) void flash_f16(
    const __half* __restrict__ qkv, __half* __restrict__ y)
{
    extern __shared__ char smc[];
    const uint32_t sb = (uint32_t)__cvta_generic_to_shared(smc);
    const int qt = gridDim.x - 1 - blockIdx.x;
    const int b = blockIdx.y >> 4, h = blockIdx.y & 15;
    const int tid = threadIdx.x, wid = tid >> 5, lane = tid & 31;
    const int gr = lane >> 2, gc = lane & 3;
    const int g8 = lane >> 3, r8 = lane & 7;
    const int C3 = 3 * N_EMBD;
    const int q0 = qt * 128;
    const __half* gb = qkv + (size_t)(b * SEQ) * C3 + h * HS;
    const int jmax = 2 * qt + 1;

    auto issue_kv = [&](int j) {
        const int p3 = j % 3, kb = j * 64;
        #pragma unroll
        for (int i = 0; i < 2; i++) {
            int u = tid + 256 * i, r = u >> 3, cu = u & 7;
            uint32_t d = (uint32_t)(r * 128 + ((cu ^ (r & 7)) << 4)) + p3 * 8192;
            cp_async16(sb + FK_OFF + d, gb + N_EMBD + (size_t)(kb + r) * C3 + cu * 8);
            cp_async16(sb + FV_OFF + d, gb + 2 * N_EMBD + (size_t)(kb + r) * C3 + cu * 8);
        }
        CP_COMMIT();
    };

    {
        #pragma unroll
        for (int i = 0; i < 4; i++) {
            int u = tid + 256 * i, r = u >> 3, cu = u & 7;
            cp_async16(sb + FQ_OFF + r * 128 + ((cu ^ (r & 7)) << 4),
                       gb + (size_t)(q0 + r) * C3 + cu * 8);
        }
        #pragma unroll
        for (int i = 0; i < 2; i++) {
            int u = tid + 256 * i, r = u >> 3, cu = u & 7;
            uint32_t d = (uint32_t)(r * 128 + ((cu ^ (r & 7)) << 4));
            cp_async16(sb + FK_OFF + d, gb + N_EMBD + (size_t)r * C3 + cu * 8);
            cp_async16(sb + FV_OFF + d, gb + 2 * N_EMBD + (size_t)r * C3 + cu * 8);
        }
        CP_COMMIT();
        issue_kv(1);
    }

    uint32_t qa[4][4];
    float o[8][4];
    #pragma unroll
    for (int t = 0; t < 8; t++)
        #pragma unroll
        for (int r = 0; r < 4; r++) o[t][r] = 0.f;
    float m0 = -1e30f, m1 = -1e30f, l0 = 0.f, l1 = 0.f;
    const int r0 = q0 + wid * 16 + gr, r1 = r0 + 8;

    for (int j = 0; j <= jmax; j++) {
        if (j == jmax) { CP_WAIT0(); } else { CP_WAIT1(); }
        __syncthreads();
        if (j + 2 <= jmax) issue_kv(j + 2);

        if (j == 0) {
            #pragma unroll
            for (int ks = 0; ks < 4; ks++) {
                int row = wid * 16 + (g8 & 1) * 8 + r8;
                int unit = 2 * ks + (g8 >> 1);
                LDSM4(qa[ks][0], qa[ks][1], qa[ks][2], qa[ks][3],
                      sb + FQ_OFF + row * 128 + ((unit ^ (row & 7)) << 4));
            }
        }

        const int p3 = j % 3, kb = j * 64;
        if (kb <= q0 + wid * 16 + 15) {
            const uint32_t Kb = sb + FK_OFF + p3 * 8192;
            float s[8][4];
            #pragma unroll
            for (int t = 0; t < 8; t++)
                #pragma unroll
                for (int r = 0; r < 4; r++) s[t][r] = 0.f;
            #pragma unroll
            for (int t = 0; t < 8; t++) {
                uint32_t bfr[8];
                #pragma unroll
                for (int kp = 0; kp < 2; kp++) {
                    int row = 8 * t + r8;
                    int unit = 4 * kp + g8;
                    LDSM4(bfr[4 * kp], bfr[4 * kp + 1], bfr[4 * kp + 2], bfr[4 * kp + 3],
                          Kb + row * 128 + ((unit ^ (row & 7)) << 4));
                }
                #pragma unroll
                for (int ks = 0; ks < 4; ks++)
                    mma_f16(s[t], qa[ks], &bfr[2 * ks]);
            }
            // ---- mask (near-diagonal only) + online softmax in exp2 domain
            float tm0 = -1e30f, tm1 = -1e30f;
            if (kb + 63 < q0 + wid * 16) {   // warp-uniform fully-unmasked tile
                #pragma unroll
                for (int t = 0; t < 8; t++) {
                    tm0 = fmaxf(tm0, fmaxf(s[t][0], s[t][1]));
                    tm1 = fmaxf(tm1, fmaxf(s[t][2], s[t][3]));
                }
            } else {
                #pragma unroll
                for (int t = 0; t < 8; t++) {
                    const int c0 = kb + 8 * t + 2 * gc, c1 = c0 + 1;
                    s[t][0] = (c0 <= r0) ? s[t][0] : -1e30f;
                    s[t][1] = (c1 <= r0) ? s[t][1] : -1e30f;
                    s[t][2] = (c0 <= r1) ? s[t][2] : -1e30f;
                    s[t][3] = (c1 <= r1) ? s[t][3] : -1e30f;
                    tm0 = fmaxf(tm0, fmaxf(s[t][0], s[t][1]));
                    tm1 = fmaxf(tm1, fmaxf(s[t][2], s[t][3]));
                }
            }
            #pragma unroll
            for (int off = 1; off <= 2; off <<= 1) {
                tm0 = fmaxf(tm0, __shfl_xor_sync(0xffffffffu, tm0, off));
                tm1 = fmaxf(tm1, __shfl_xor_sync(0xffffffffu, tm1, off));
            }
            const float m0n = fmaxf(m0, tm0), m1n = fmaxf(m1, tm1);
            uint32_t pa[4][4];
            float rs0 = 0.f, rs1 = 0.f;
            #pragma unroll
            for (int t = 0; t < 8; t++) {
                float p0 = ex2f(s[t][0] - m0n);
                float p1 = ex2f(s[t][1] - m0n);
                float p2 = ex2f(s[t][2] - m1n);
                float p3f = ex2f(s[t][3] - m1n);
                rs0 += p0 + p1;
                rs1 += p2 + p3f;
                const int ks = t >> 1, hi = (t & 1) * 2;
                pa[ks][hi] = pack_h2(p0, p1);
                pa[ks][hi + 1] = pack_h2(p2, p3f);
            }
            #pragma unroll
            for (int off = 1; off <= 2; off <<= 1) {
                rs0 += __shfl_xor_sync(0xffffffffu, rs0, off);
                rs1 += __shfl_xor_sync(0xffffffffu, rs1, off);
            }
            const float c0f = ex2f(m0 - m0n), c1f = ex2f(m1 - m1n);
            l0 = l0 * c0f + rs0;
            l1 = l1 * c1f + rs1;
            m0 = m0n; m1 = m1n;
            #pragma unroll
            for (int t = 0; t < 8; t++) {
                o[t][0] *= c0f; o[t][1] *= c0f;
                o[t][2] *= c1f; o[t][3] *= c1f;
            }
            const uint32_t Vb = sb + FV_OFF + p3 * 8192;
            #pragma unroll
            for (int tp = 0; tp < 4; tp++) {
                #pragma unroll
                for (int ks = 0; ks < 4; ks++) {
                    uint32_t bv[4];
                    int row = 16 * ks + (g8 & 1) * 8 + r8;
                    int unit = 2 * tp + (g8 >> 1);
                    LDSM4T(bv[0], bv[1], bv[2], bv[3],
                           Vb + row * 128 + ((unit ^ (row & 7)) << 4));
                    mma_f16(o[2 * tp], pa[ks], &bv[0]);
                    mma_f16(o[2 * tp + 1], pa[ks], &bv[2]);
                }
            }
        }
    }

    const float i0 = 1.f / l0, i1 = 1.f / l1;
    __half* y0 = y + (size_t)(b * SEQ + r0) * N_EMBD + h * HS;
    __half* y1 = y + (size_t)(b * SEQ + r1) * N_EMBD + h * HS;
    #pragma unroll
    for (int t = 0; t < 8; t++) {
        *(__half2*)(y0 + 8 * t + 2 * gc) = __floats2half2_rn(o[t][0] * i0, o[t][1] * i0);
        *(__half2*)(y1 + 8 * t + 2 * gc) = __floats2half2_rn(o[t][2] * i1, o[t][3] * i1);
    }
}

// ---------------------------------------------------------------------------
extern "C" void kernel_launch(void* const* d_in, const int* in_sizes, int n_in,
                              void* d_out, int out_size)
{
    const float* x      = (const float*)d_in[0];
    const float* w_attn = (const float*)d_in[1];
    const float* w_proj = (const float*)d_in[2];
    float* out = (float*)d_out;

    __half *xh, *qkvh, *yh, *wta, *wtp;
    cudaGetSymbolAddress((void**)&xh, g_xh);
    cudaGetSymbolAddress((void**)&qkvh, g_qkvh);
    cudaGetSymbolAddress((void**)&yh, g_yh);
    cudaGetSymbolAddress((void**)&wta, g_wta_h);
    cudaGetSymbolAddress((void**)&wtp, g_wtp_h);

    cudaFuncSetAttribute(gemm_f16<true>, cudaFuncAttributeMaxDynamicSharedMemorySize, GEMM_SMEM);
    cudaFuncSetAttribute(gemm_f16<false>, cudaFuncAttributeMaxDynamicSharedMemorySize, GEMM_SMEM);
    cudaFuncSetAttribute(flash_f16, cudaFuncAttributeMaxDynamicSharedMemorySize, FLASH_SMEM);

    const int n4 = MTOT * N_EMBD / 4;
    cvt_half4<<<n4 / 256, 256>>>((const float4*)x, (__half2*)xh, n4);
    transpose_cvt<<<dim3(3 * N_EMBD / 32, N_EMBD / 32), 256>>>(w_attn, wta, N_EMBD, 3 * N_EMBD);
    transpose_cvt<<<dim3(N_EMBD / 32, N_EMBD / 32), 256>>>(w_proj, wtp, N_EMBD, N_EMBD);

    gemm_f16<true><<<dim3(3 * N_EMBD / 128, MTOT / 128), 256, GEMM_SMEM>>>(
        xh, wta, qkvh, MTOT, 3 * N_EMBD, N_EMBD, 1);

    flash_f16<<<dim3(SEQ / 128, BATCH * N_HEAD), 256, FLASH_SMEM>>>(qkvh, yh);

    gemm_f16<false><<<dim3(N_EMBD / 128, MTOT / 128), 256, GEMM_SMEM>>>(
        yh, wtp, out, MTOT, N_EMBD, N_EMBD, 0);
}

// round 14
// speedup vs baseline: 13.8499x; 1.0492x over previous
// R14: flash softmax via ex2.approx.f16x2 (P produced directly in fp16) +
// row-sum-by-MMA against ones (no scalar l reduction). GEMMs unchanged (R13).
#include <cuda_runtime.h>
#include <cuda_fp16.h>
#include <math.h>
#include <stdint.h>

#define N_EMBD 1024
#define N_HEAD 16
#define HS 64
#define BATCH 4
#define SEQ 2048
#define MTOT (BATCH * SEQ)

__device__ __half g_xh[(size_t)MTOT * N_EMBD];
__device__ __half g_qkvh[(size_t)MTOT * 3 * N_EMBD];
__device__ __half g_yh[(size_t)MTOT * N_EMBD];
__device__ __half g_wta_h[(size_t)3 * N_EMBD * N_EMBD];
__device__ __half g_wtp_h[(size_t)N_EMBD * N_EMBD];

// ---------------------------------------------------------------------------
__device__ __forceinline__ void cp_async16(uint32_t dst, const void* src) {
    asm volatile("cp.async.cg.shared.global [%0], [%1], 16;" :: "r"(dst), "l"(src));
}
#define CP_COMMIT() asm volatile("cp.async.commit_group;" ::: "memory")
#define CP_WAIT0() asm volatile("cp.async.wait_group 0;" ::: "memory")
#define CP_WAIT1() asm volatile("cp.async.wait_group 1;" ::: "memory")

#define LDSM4(r0, r1, r2, r3, addr) \
    asm volatile("ldmatrix.sync.aligned.m8n8.x4.shared.b16 {%0,%1,%2,%3}, [%4];" \
                 : "=r"(r0), "=r"(r1), "=r"(r2), "=r"(r3) : "r"(addr))
#define LDSM4T(r0, r1, r2, r3, addr) \
    asm volatile("ldmatrix.sync.aligned.m8n8.x4.trans.shared.b16 {%0,%1,%2,%3}, [%4];" \
                 : "=r"(r0), "=r"(r1), "=r"(r2), "=r"(r3) : "r"(addr))

__device__ __forceinline__ void mma_f16(float* c, const uint32_t* a, const uint32_t* b) {
    asm volatile(
        "mma.sync.aligned.m16n8k16.row.col.f32.f16.f16.f32 "
        "{%0,%1,%2,%3}, {%4,%5,%6,%7}, {%8,%9}, {%0,%1,%2,%3};"
        : "+f"(c[0]), "+f"(c[1]), "+f"(c[2]), "+f"(c[3])
        : "r"(a[0]), "r"(a[1]), "r"(a[2]), "r"(a[3]), "r"(b[0]), "r"(b[1]));
}

__device__ __forceinline__ uint32_t pack_h2(float a, float b) {
    __half2 h = __floats2half2_rn(a, b);
    return *reinterpret_cast<uint32_t*>(&h);
}
__device__ __forceinline__ float ex2f(float x) {
    float r;
    asm("ex2.approx.f32 %0, %1;" : "=f"(r) : "f"(x));
    return r;
}
__device__ __forceinline__ uint32_t ex2_h2(uint32_t d) {
    uint32_t r;
    asm("ex2.approx.f16x2 %0, %1;" : "=r"(r) : "r"(d));
    return r;
}

// ---------------------------------------------------------------------------
__global__ __launch_bounds__(256) void cvt_half4(
    const float4* __restrict__ in, __half2* __restrict__ out, int n4)
{
    int i = blockIdx.x * blockDim.x + threadIdx.x;
    if (i < n4) {
        float4 v = in[i];
        out[2 * i] = __floats2half2_rn(v.x, v.y);
        out[2 * i + 1] = __floats2half2_rn(v.z, v.w);
    }
}

__global__ __launch_bounds__(256) void transpose_cvt(
    const float* __restrict__ in, __half* __restrict__ out, int R, int C)
{
    __shared__ float t[32][33];
    const int bx = blockIdx.x * 32, by = blockIdx.y * 32;
    const int tx = threadIdx.x & 31, ty = threadIdx.x >> 5;
    #pragma unroll
    for (int i = ty; i < 32; i += 8)
        t[i][tx] = in[(size_t)(by + i) * C + bx + tx];
    __syncthreads();
    #pragma unroll
    for (int i = ty; i < 32; i += 8)
        out[(size_t)(bx + i) * R + by + tx] = __float2half_rn(t[tx][i]);
}

// ---------------------------------------------------------------------------
// fp16 GEMM (R6/R13 structure: 2-stage cp.async, simple inner loop).
// ---------------------------------------------------------------------------
#define GEMM_SMEM 65536
#define QSCALE (0.125f * 1.4426950408889634f)

template <bool HALF_OUT>
__global__ __launch_bounds__(256, 2) void gemm_f16(
    const __half* __restrict__ A, const __half* __restrict__ Bt,
    void* __restrict__ Cv, int M, int N, int K, int scaleQ)
{
    extern __shared__ char smc[];
    const uint32_t sb = (uint32_t)__cvta_generic_to_shared(smc);
    const int tid = threadIdx.x, wid = tid >> 5, lane = tid & 31;
    const int gr = lane >> 2, gc = lane & 3;
    const int g8 = lane >> 3, r8 = lane & 7;
    const int wm = (wid & 1) * 64, wn = (wid >> 1) * 32;

    const __half* Ag = A + (size_t)blockIdx.y * 128 * K;
    const __half* Bg = Bt + (size_t)blockIdx.x * 128 * K;

    float acc[4][4][4];
    #pragma unroll
    for (int i = 0; i < 4; i++)
        #pragma unroll
        for (int j = 0; j < 4; j++)
            #pragma unroll
            for (int r = 0; r < 4; r++) acc[i][j][r] = 0.f;

    auto issue = [&](int c) {
        const int p = c & 1, k0 = c * 64;
        const uint32_t aB = sb + p * 32768, bB = aB + 16384;
        #pragma unroll
        for (int i = 0; i < 4; i++) {
            int u = tid + 256 * i, r = u >> 3, cu = u & 7;
            uint32_t d = (uint32_t)(r * 128 + ((cu ^ (r & 7)) << 4));
            cp_async16(aB + d, Ag + (size_t)r * K + k0 + cu * 8);
            cp_async16(bB + d, Bg + (size_t)r * K + k0 + cu * 8);
        }
        CP_COMMIT();
    };

    issue(0);
    const int NCH = K / 64;
    for (int c = 0; c < NCH; c++) {
        const int p = c & 1;
        if (c + 1 < NCH) { issue(c + 1); CP_WAIT1(); } else { CP_WAIT0(); }
        __syncthreads();
        const uint32_t aB = sb + p * 32768, bB = aB + 16384;

        #pragma unroll
        for (int ks = 0; ks < 4; ks++) {
            uint32_t a[4][4], b[4][2];
            #pragma unroll
            for (int i = 0; i < 4; i++) {
                int row = wm + i * 16 + (g8 & 1) * 8 + r8;
                int unit = 2 * ks + (g8 >> 1);
                LDSM4(a[i][0], a[i][1], a[i][2], a[i][3],
                      aB + row * 128 + ((unit ^ (row & 7)) << 4));
            }
            #pragma unroll
            for (int jp = 0; jp < 2; jp++) {
                int row = wn + jp * 16 + (g8 >> 1) * 8 + r8;
                int unit = 2 * ks + (g8 & 1);
                LDSM4(b[2 * jp][0], b[2 * jp][1], b[2 * jp + 1][0], b[2 * jp + 1][1],
                      bB + row * 128 + ((unit ^ (row & 7)) << 4));
            }
            #pragma unroll
            for (int i = 0; i < 4; i++)
                #pragma unroll
                for (int j = 0; j < 4; j++)
                    mma_f16(acc[i][j], a[i], b[j]);
        }
        __syncthreads();
    }

    const float sc = (scaleQ && blockIdx.x < 8) ? QSCALE : 1.0f;
    if (HALF_OUT) {
        __half* Ch = (__half*)Cv + (size_t)(blockIdx.y * 128 + wm) * N + blockIdx.x * 128 + wn;
        #pragma unroll
        for (int i = 0; i < 4; i++)
            #pragma unroll
            for (int j = 0; j < 4; j++) {
                *(__half2*)(Ch + (size_t)(i * 16 + gr) * N + j * 8 + 2 * gc) =
                    __floats2half2_rn(acc[i][j][0] * sc, acc[i][j][1] * sc);
                *(__half2*)(Ch + (size_t)(i * 16 + gr + 8) * N + j * 8 + 2 * gc) =
                    __floats2half2_rn(acc[i][j][2] * sc, acc[i][j][3] * sc);
            }
    } else {
        float* Cf = (float*)Cv + (size_t)(blockIdx.y * 128 + wm) * N + blockIdx.x * 128 + wn;
        #pragma unroll
        for (int i = 0; i < 4; i++)
            #pragma unroll
            for (int j = 0; j < 4; j++) {
                *(float2*)(Cf + (size_t)(i * 16 + gr) * N + j * 8 + 2 * gc) =
                    make_float2(acc[i][j][0], acc[i][j][1]);
                *(float2*)(Cf + (size_t)(i * 16 + gr + 8) * N + j * 8 + 2 * gc) =
                    make_float2(acc[i][j][2], acc[i][j][3]);
            }
    }
}

// ---------------------------------------------------------------------------
// fp16 flash attention (causal), exp2-domain softmax with f16x2 ex2 and
// l computed by MMA row-sum against a ones fragment.
// ---------------------------------------------------------------------------
#define FQ_OFF 0
#define FK_OFF 16384
#define FV_OFF (16384 + 3 * 8192)
#define FLASH_SMEM 65536
#define MASKF (-60000.0f)

__global__ __launch_bounds__(256, 2) void flash_f16(
    const __half* __restrict__ qkv, __half* __restrict__ y)
{
    extern __shared__ char smc[];
    const uint32_t sb = (uint32_t)__cvta_generic_to_shared(smc);
    const int qt = gridDim.x - 1 - blockIdx.x;
    const int b = blockIdx.y >> 4, h = blockIdx.y & 15;
    const int tid = threadIdx.x, wid = tid >> 5, lane = tid & 31;
    const int gr = lane >> 2, gc = lane & 3;
    const int g8 = lane >> 3, r8 = lane & 7;
    const int C3 = 3 * N_EMBD;
    const int q0 = qt * 128;
    const __half* gb = qkv + (size_t)(b * SEQ) * C3 + h * HS;
    const int jmax = 2 * qt + 1;

    auto issue_kv = [&](int j) {
        const int p3 = j % 3, kb = j * 64;
        #pragma unroll
        for (int i = 0; i < 2; i++) {
            int u = tid + 256 * i, r = u >> 3, cu = u & 7;
            uint32_t d = (uint32_t)(r * 128 + ((cu ^ (r & 7)) << 4)) + p3 * 8192;
            cp_async16(sb + FK_OFF + d, gb + N_EMBD + (size_t)(kb + r) * C3 + cu * 8);
            cp_async16(sb + FV_OFF + d, gb + 2 * N_EMBD + (size_t)(kb + r) * C3 + cu * 8);
        }
        CP_COMMIT();
    };

    {
        #pragma unroll
        for (int i = 0; i < 4; i++) {
            int u = tid + 256 * i, r = u >> 3, cu = u & 7;
            cp_async16(sb + FQ_OFF + r * 128 + ((cu ^ (r & 7)) << 4),
                       gb + (size_t)(q0 + r) * C3 + cu * 8);
        }
        #pragma unroll
        for (int i = 0; i < 2; i++) {
            int u = tid + 256 * i, r = u >> 3, cu = u & 7;
            uint32_t d = (uint32_t)(r * 128 + ((cu ^ (r & 7)) << 4));
            cp_async16(sb + FK_OFF + d, gb + N_EMBD + (size_t)r * C3 + cu * 8);
            cp_async16(sb + FV_OFF + d, gb + 2 * N_EMBD + (size_t)r * C3 + cu * 8);
        }
        CP_COMMIT();
        issue_kv(1);
    }

    uint32_t qa[4][4];
    float o[8][4];
    #pragma unroll
    for (int t = 0; t < 8; t++)
        #pragma unroll
        for (int r = 0; r < 4; r++) o[t][r] = 0.f;
    float lrow[4] = {0.f, 0.f, 0.f, 0.f};   // MMA row-sum accumulator (cols equal)
    float m0 = -1e30f, m1 = -1e30f;
    const int r0 = q0 + wid * 16 + gr, r1 = r0 + 8;
    const uint32_t onesb[2] = {0x3C003C00u, 0x3C003C00u};   // fp16 1.0 x2

    for (int j = 0; j <= jmax; j++) {
        if (j == jmax) { CP_WAIT0(); } else { CP_WAIT1(); }
        __syncthreads();
        if (j + 2 <= jmax) issue_kv(j + 2);

        if (j == 0) {
            #pragma unroll
            for (int ks = 0; ks < 4; ks++) {
                int row = wid * 16 + (g8 & 1) * 8 + r8;
                int unit = 2 * ks + (g8 >> 1);
                LDSM4(qa[ks][0], qa[ks][1], qa[ks][2], qa[ks][3],
                      sb + FQ_OFF + row * 128 + ((unit ^ (row & 7)) << 4));
            }
        }

        const int p3 = j % 3, kb = j * 64;
        if (kb <= q0 + wid * 16 + 15) {
            const uint32_t Kb = sb + FK_OFF + p3 * 8192;
            float s[8][4];
            #pragma unroll
            for (int t = 0; t < 8; t++)
                #pragma unroll
                for (int r = 0; r < 4; r++) s[t][r] = 0.f;
            #pragma unroll
            for (int t = 0; t < 8; t++) {
                uint32_t bfr[8];
                #pragma unroll
                for (int kp = 0; kp < 2; kp++) {
                    int row = 8 * t + r8;
                    int unit = 4 * kp + g8;
                    LDSM4(bfr[4 * kp], bfr[4 * kp + 1], bfr[4 * kp + 2], bfr[4 * kp + 3],
                          Kb + row * 128 + ((unit ^ (row & 7)) << 4));
                }
                #pragma unroll
                for (int ks = 0; ks < 4; ks++)
                    mma_f16(s[t], qa[ks], &bfr[2 * ks]);
            }
            // ---- mask (near-diagonal only) + row max
            float tm0 = -1e30f, tm1 = -1e30f;
            if (kb + 63 < q0 + wid * 16) {
                #pragma unroll
                for (int t = 0; t < 8; t++) {
                    tm0 = fmaxf(tm0, fmaxf(s[t][0], s[t][1]));
                    tm1 = fmaxf(tm1, fmaxf(s[t][2], s[t][3]));
                }
            } else {
                #pragma unroll
                for (int t = 0; t < 8; t++) {
                    const int c0 = kb + 8 * t + 2 * gc, c1 = c0 + 1;
                    s[t][0] = (c0 <= r0) ? s[t][0] : MASKF;
                    s[t][1] = (c1 <= r0) ? s[t][1] : MASKF;
                    s[t][2] = (c0 <= r1) ? s[t][2] : MASKF;
                    s[t][3] = (c1 <= r1) ? s[t][3] : MASKF;
                    tm0 = fmaxf(tm0, fmaxf(s[t][0], s[t][1]));
                    tm1 = fmaxf(tm1, fmaxf(s[t][2], s[t][3]));
                }
            }
            #pragma unroll
            for (int off = 1; off <= 2; off <<= 1) {
                tm0 = fmaxf(tm0, __shfl_xor_sync(0xffffffffu, tm0, off));
                tm1 = fmaxf(tm1, __shfl_xor_sync(0xffffffffu, tm1, off));
            }
            const float m0n = fmaxf(m0, tm0), m1n = fmaxf(m1, tm1);
            // ---- P = ex2(s - m) computed directly in fp16 pairs
            uint32_t pa[4][4];
            #pragma unroll
            for (int t = 0; t < 8; t++) {
                const int ks = t >> 1, hi = (t & 1) * 2;
                pa[ks][hi]     = ex2_h2(pack_h2(s[t][0] - m0n, s[t][1] - m0n));
                pa[ks][hi + 1] = ex2_h2(pack_h2(s[t][2] - m1n, s[t][3] - m1n));
            }
            const float c0f = ex2f(m0 - m0n), c1f = ex2f(m1 - m1n);
            m0 = m0n; m1 = m1n;
            lrow[0] *= c0f; lrow[1] *= c0f;
            lrow[2] *= c1f; lrow[3] *= c1f;
            #pragma unroll
            for (int t = 0; t < 8; t++) {
                o[t][0] *= c0f; o[t][1] *= c0f;
                o[t][2] *= c1f; o[t][3] *= c1f;
            }
            // ---- l += P @ ones  (row sum lands in every output column)
            #pragma unroll
            for (int ks = 0; ks < 4; ks++)
                mma_f16(lrow, pa[ks], onesb);
            // ---- O += P V
            const uint32_t Vb = sb + FV_OFF + p3 * 8192;
            #pragma unroll
            for (int tp = 0; tp < 4; tp++) {
                #pragma unroll
                for (int ks = 0; ks < 4; ks++) {
                    uint32_t bv[4];
                    int row = 16 * ks + (g8 & 1) * 8 + r8;
                    int unit = 2 * tp + (g8 >> 1);
                    LDSM4T(bv[0], bv[1], bv[2], bv[3],
                           Vb + row * 128 + ((unit ^ (row & 7)) << 4));
                    mma_f16(o[2 * tp], pa[ks], &bv[0]);
                    mma_f16(o[2 * tp + 1], pa[ks], &bv[2]);
                }
            }
        }
    }

    const float i0 = 1.f / lrow[0], i1 = 1.f / lrow[2];
    __half* y0 = y + (size_t)(b * SEQ + r0) * N_EMBD + h * HS;
    __half* y1 = y + (size_t)(b * SEQ + r1) * N_EMBD + h * HS;
    #pragma unroll
    for (int t = 0; t < 8; t++) {
        *(__half2*)(y0 + 8 * t + 2 * gc) = __floats2half2_rn(o[t][0] * i0, o[t][1] * i0);
        *(__half2*)(y1 + 8 * t + 2 * gc) = __floats2half2_rn(o[t][2] * i1, o[t][3] * i1);
    }
}

// ---------------------------------------------------------------------------
extern "C" void kernel_launch(void* const* d_in, const int* in_sizes, int n_in,
                              void* d_out, int out_size)
{
    const float* x      = (const float*)d_in[0];
    const float* w_attn = (const float*)d_in[1];
    const float* w_proj = (const float*)d_in[2];
    float* out = (float*)d_out;

    __half *xh, *qkvh, *yh, *wta, *wtp;
    cudaGetSymbolAddress((void**)&xh, g_xh);
    cudaGetSymbolAddress((void**)&qkvh, g_qkvh);
    cudaGetSymbolAddress((void**)&yh, g_yh);
    cudaGetSymbolAddress((void**)&wta, g_wta_h);
    cudaGetSymbolAddress((void**)&wtp, g_wtp_h);

    cudaFuncSetAttribute(gemm_f16<true>, cudaFuncAttributeMaxDynamicSharedMemorySize, GEMM_SMEM);
    cudaFuncSetAttribute(gemm_f16<false>, cudaFuncAttributeMaxDynamicSharedMemorySize, GEMM_SMEM);
    cudaFuncSetAttribute(flash_f16, cudaFuncAttributeMaxDynamicSharedMemorySize, FLASH_SMEM);

    const int n4 = MTOT * N_EMBD / 4;
    cvt_half4<<<n4 / 256, 256>>>((const float4*)x, (__half2*)xh, n4);
    transpose_cvt<<<dim3(3 * N_EMBD / 32, N_EMBD / 32), 256>>>(w_attn, wta, N_EMBD, 3 * N_EMBD);
    transpose_cvt<<<dim3(N_EMBD / 32, N_EMBD / 32), 256>>>(w_proj, wtp, N_EMBD, N_EMBD);

    gemm_f16<true><<<dim3(3 * N_EMBD / 128, MTOT / 128), 256, GEMM_SMEM>>>(
        xh, wta, qkvh, MTOT, 3 * N_EMBD, N_EMBD, 1);

    flash_f16<<<dim3(SEQ / 128, BATCH * N_HEAD), 256, FLASH_SMEM>>>(qkvh, yh);

    gemm_f16<false><<<dim3(N_EMBD / 128, MTOT / 128), 256, GEMM_SMEM>>>(
        yh, wtp, out, MTOT, N_EMBD, N_EMBD, 0);
}

// round 15
// speedup vs baseline: 14.3665x; 1.0373x over previous
// R15: flash re-partitioned to 4 warps x 32 query rows (128 threads) —
// halves K/V fragment LDS duplication (smem-crossbar bound per R14 model).
// GEMMs + prep unchanged from R14.
#include <cuda_runtime.h>
#include <cuda_fp16.h>
#include <math.h>
#include <stdint.h>

#define N_EMBD 1024
#define N_HEAD 16
#define HS 64
#define BATCH 4
#define SEQ 2048
#define MTOT (BATCH * SEQ)

__device__ __half g_xh[(size_t)MTOT * N_EMBD];
__device__ __half g_qkvh[(size_t)MTOT * 3 * N_EMBD];
__device__ __half g_yh[(size_t)MTOT * N_EMBD];
__device__ __half g_wta_h[(size_t)3 * N_EMBD * N_EMBD];
__device__ __half g_wtp_h[(size_t)N_EMBD * N_EMBD];

// ---------------------------------------------------------------------------
__device__ __forceinline__ void cp_async16(uint32_t dst, const void* src) {
    asm volatile("cp.async.cg.shared.global [%0], [%1], 16;" :: "r"(dst), "l"(src));
}
#define CP_COMMIT() asm volatile("cp.async.commit_group;" ::: "memory")
#define CP_WAIT0() asm volatile("cp.async.wait_group 0;" ::: "memory")
#define CP_WAIT1() asm volatile("cp.async.wait_group 1;" ::: "memory")

#define LDSM4(r0, r1, r2, r3, addr) \
    asm volatile("ldmatrix.sync.aligned.m8n8.x4.shared.b16 {%0,%1,%2,%3}, [%4];" \
                 : "=r"(r0), "=r"(r1), "=r"(r2), "=r"(r3) : "r"(addr))
#define LDSM4T(r0, r1, r2, r3, addr) \
    asm volatile("ldmatrix.sync.aligned.m8n8.x4.trans.shared.b16 {%0,%1,%2,%3}, [%4];" \
                 : "=r"(r0), "=r"(r1), "=r"(r2), "=r"(r3) : "r"(addr))

__device__ __forceinline__ void mma_f16(float* c, const uint32_t* a, const uint32_t* b) {
    asm volatile(
        "mma.sync.aligned.m16n8k16.row.col.f32.f16.f16.f32 "
        "{%0,%1,%2,%3}, {%4,%5,%6,%7}, {%8,%9}, {%0,%1,%2,%3};"
        : "+f"(c[0]), "+f"(c[1]), "+f"(c[2]), "+f"(c[3])
        : "r"(a[0]), "r"(a[1]), "r"(a[2]), "r"(a[3]), "r"(b[0]), "r"(b[1]));
}

__device__ __forceinline__ uint32_t pack_h2(float a, float b) {
    __half2 h = __floats2half2_rn(a, b);
    return *reinterpret_cast<uint32_t*>(&h);
}
__device__ __forceinline__ float ex2f(float x) {
    float r;
    asm("ex2.approx.f32 %0, %1;" : "=f"(r) : "f"(x));
    return r;
}
__device__ __forceinline__ uint32_t ex2_h2(uint32_t d) {
    uint32_t r;
    asm("ex2.approx.f16x2 %0, %1;" : "=r"(r) : "r"(d));
    return r;
}

// ---------------------------------------------------------------------------
__global__ __launch_bounds__(256) void cvt_half4(
    const float4* __restrict__ in, __half2* __restrict__ out, int n4)
{
    int i = blockIdx.x * blockDim.x + threadIdx.x;
    if (i < n4) {
        float4 v = in[i];
        out[2 * i] = __floats2half2_rn(v.x, v.y);
        out[2 * i + 1] = __floats2half2_rn(v.z, v.w);
    }
}

__global__ __launch_bounds__(256) void transpose_cvt(
    const float* __restrict__ in, __half* __restrict__ out, int R, int C)
{
    __shared__ float t[32][33];
    const int bx = blockIdx.x * 32, by = blockIdx.y * 32;
    const int tx = threadIdx.x & 31, ty = threadIdx.x >> 5;
    #pragma unroll
    for (int i = ty; i < 32; i += 8)
        t[i][tx] = in[(size_t)(by + i) * C + bx + tx];
    __syncthreads();
    #pragma unroll
    for (int i = ty; i < 32; i += 8)
        out[(size_t)(bx + i) * R + by + tx] = __float2half_rn(t[tx][i]);
}

// ---------------------------------------------------------------------------
// fp16 GEMM (R6/R13 structure, unchanged).
// ---------------------------------------------------------------------------
#define GEMM_SMEM 65536
#define QSCALE (0.125f * 1.4426950408889634f)

template <bool HALF_OUT>
__global__ __launch_bounds__(256, 2) void gemm_f16(
    const __half* __restrict__ A, const __half* __restrict__ Bt,
    void* __restrict__ Cv, int M, int N, int K, int scaleQ)
{
    extern __shared__ char smc[];
    const uint32_t sb = (uint32_t)__cvta_generic_to_shared(smc);
    const int tid = threadIdx.x, wid = tid >> 5, lane = tid & 31;
    const int gr = lane >> 2, gc = lane & 3;
    const int g8 = lane >> 3, r8 = lane & 7;
    const int wm = (wid & 1) * 64, wn = (wid >> 1) * 32;

    const __half* Ag = A + (size_t)blockIdx.y * 128 * K;
    const __half* Bg = Bt + (size_t)blockIdx.x * 128 * K;

    float acc[4][4][4];
    #pragma unroll
    for (int i = 0; i < 4; i++)
        #pragma unroll
        for (int j = 0; j < 4; j++)
            #pragma unroll
            for (int r = 0; r < 4; r++) acc[i][j][r] = 0.f;

    auto issue = [&](int c) {
        const int p = c & 1, k0 = c * 64;
        const uint32_t aB = sb + p * 32768, bB = aB + 16384;
        #pragma unroll
        for (int i = 0; i < 4; i++) {
            int u = tid + 256 * i, r = u >> 3, cu = u & 7;
            uint32_t d = (uint32_t)(r * 128 + ((cu ^ (r & 7)) << 4));
            cp_async16(aB + d, Ag + (size_t)r * K + k0 + cu * 8);
            cp_async16(bB + d, Bg + (size_t)r * K + k0 + cu * 8);
        }
        CP_COMMIT();
    };

    issue(0);
    const int NCH = K / 64;
    for (int c = 0; c < NCH; c++) {
        const int p = c & 1;
        if (c + 1 < NCH) { issue(c + 1); CP_WAIT1(); } else { CP_WAIT0(); }
        __syncthreads();
        const uint32_t aB = sb + p * 32768, bB = aB + 16384;

        #pragma unroll
        for (int ks = 0; ks < 4; ks++) {
            uint32_t a[4][4], b[4][2];
            #pragma unroll
            for (int i = 0; i < 4; i++) {
                int row = wm + i * 16 + (g8 & 1) * 8 + r8;
                int unit = 2 * ks + (g8 >> 1);
                LDSM4(a[i][0], a[i][1], a[i][2], a[i][3],
                      aB + row * 128 + ((unit ^ (row & 7)) << 4));
            }
            #pragma unroll
            for (int jp = 0; jp < 2; jp++) {
                int row = wn + jp * 16 + (g8 >> 1) * 8 + r8;
                int unit = 2 * ks + (g8 & 1);
                LDSM4(b[2 * jp][0], b[2 * jp][1], b[2 * jp + 1][0], b[2 * jp + 1][1],
                      bB + row * 128 + ((unit ^ (row & 7)) << 4));
            }
            #pragma unroll
            for (int i = 0; i < 4; i++)
                #pragma unroll
                for (int j = 0; j < 4; j++)
                    mma_f16(acc[i][j], a[i], b[j]);
        }
        __syncthreads();
    }

    const float sc = (scaleQ && blockIdx.x < 8) ? QSCALE : 1.0f;
    if (HALF_OUT) {
        __half* Ch = (__half*)Cv + (size_t)(blockIdx.y * 128 + wm) * N + blockIdx.x * 128 + wn;
        #pragma unroll
        for (int i = 0; i < 4; i++)
            #pragma unroll
            for (int j = 0; j < 4; j++) {
                *(__half2*)(Ch + (size_t)(i * 16 + gr) * N + j * 8 + 2 * gc) =
                    __floats2half2_rn(acc[i][j][0] * sc, acc[i][j][1] * sc);
                *(__half2*)(Ch + (size_t)(i * 16 + gr + 8) * N + j * 8 + 2 * gc) =
                    __floats2half2_rn(acc[i][j][2] * sc, acc[i][j][3] * sc);
            }
    } else {
        float* Cf = (float*)Cv + (size_t)(blockIdx.y * 128 + wm) * N + blockIdx.x * 128 + wn;
        #pragma unroll
        for (int i = 0; i < 4; i++)
            #pragma unroll
            for (int j = 0; j < 4; j++) {
                *(float2*)(Cf + (size_t)(i * 16 + gr) * N + j * 8 + 2 * gc) =
                    make_float2(acc[i][j][0], acc[i][j][1]);
                *(float2*)(Cf + (size_t)(i * 16 + gr + 8) * N + j * 8 + 2 * gc) =
                    make_float2(acc[i][j][2], acc[i][j][3]);
            }
    }
}

// ---------------------------------------------------------------------------
// fp16 flash attention (causal): 128 threads, 4 warps x 32 query rows.
// K/V fragments loaded once per warp and reused for BOTH 16-row blocks
// (halves smem crossbar traffic vs 8x16 partitioning). exp2-domain softmax
// (f16x2 ex2), l via MMA row-sum. smem: Q 16KB | K 3x8KB | V 3x8KB = 64KB.
// ---------------------------------------------------------------------------
#define FQ_OFF 0
#define FK_OFF 16384
#define FV_OFF (16384 + 3 * 8192)
#define FLASH_SMEM 65536
#define MASKF (-60000.0f)

__global__ __launch_bounds__(128, 2) void flash_f16(
    const __half* __restrict__ qkv, __half* __restrict__ y)
{
    extern __shared__ char smc[];
    const uint32_t sb = (uint32_t)__cvta_generic_to_shared(smc);
    const int qt = gridDim.x - 1 - blockIdx.x;
    const int b = blockIdx.y >> 4, h = blockIdx.y & 15;
    const int tid = threadIdx.x, wid = tid >> 5, lane = tid & 31;
    const int gr = lane >> 2, gc = lane & 3;
    const int g8 = lane >> 3, r8 = lane & 7;
    const int C3 = 3 * N_EMBD;
    const int q0 = qt * 128;
    const __half* gb = qkv + (size_t)(b * SEQ) * C3 + h * HS;
    const int jmax = 2 * qt + 1;
    const int wrow = q0 + wid * 32;   // this warp's first query row

    auto issue_kv = [&](int j) {
        const int p3 = j % 3, kb = j * 64;
        #pragma unroll
        for (int i = 0; i < 4; i++) {
            int u = tid + 128 * i, r = u >> 3, cu = u & 7;
            uint32_t d = (uint32_t)(r * 128 + ((cu ^ (r & 7)) << 4)) + p3 * 8192;
            cp_async16(sb + FK_OFF + d, gb + N_EMBD + (size_t)(kb + r) * C3 + cu * 8);
            cp_async16(sb + FV_OFF + d, gb + 2 * N_EMBD + (size_t)(kb + r) * C3 + cu * 8);
        }
        CP_COMMIT();
    };

    {
        #pragma unroll
        for (int i = 0; i < 8; i++) {
            int u = tid + 128 * i, r = u >> 3, cu = u & 7;
            cp_async16(sb + FQ_OFF + r * 128 + ((cu ^ (r & 7)) << 4),
                       gb + (size_t)(q0 + r) * C3 + cu * 8);
        }
        #pragma unroll
        for (int i = 0; i < 4; i++) {
            int u = tid + 128 * i, r = u >> 3, cu = u & 7;
            uint32_t d = (uint32_t)(r * 128 + ((cu ^ (r & 7)) << 4));
            cp_async16(sb + FK_OFF + d, gb + N_EMBD + (size_t)r * C3 + cu * 8);
            cp_async16(sb + FV_OFF + d, gb + 2 * N_EMBD + (size_t)r * C3 + cu * 8);
        }
        CP_COMMIT();
        issue_kv(1);
    }

    uint32_t qa[4][2][4];          // [ks][row-block]
    float o[2][8][4];              // [row-block][hs-octet]
    #pragma unroll
    for (int rb = 0; rb < 2; rb++)
        #pragma unroll
        for (int t = 0; t < 8; t++)
            #pragma unroll
            for (int r = 0; r < 4; r++) o[rb][t][r] = 0.f;
    float lrow[2][4] = {{0.f, 0.f, 0.f, 0.f}, {0.f, 0.f, 0.f, 0.f}};
    float m[4] = {-1e30f, -1e30f, -1e30f, -1e30f};   // 4 x 8-row groups
    const uint32_t onesb[2] = {0x3C003C00u, 0x3C003C00u};

    for (int j = 0; j <= jmax; j++) {
        if (j == jmax) { CP_WAIT0(); } else { CP_WAIT1(); }
        __syncthreads();
        if (j + 2 <= jmax) issue_kv(j + 2);

        if (j == 0) {
            #pragma unroll
            for (int ks = 0; ks < 4; ks++)
                #pragma unroll
                for (int rb = 0; rb < 2; rb++) {
                    int row = wid * 32 + rb * 16 + (g8 & 1) * 8 + r8;
                    int unit = 2 * ks + (g8 >> 1);
                    LDSM4(qa[ks][rb][0], qa[ks][rb][1], qa[ks][rb][2], qa[ks][rb][3],
                          sb + FQ_OFF + row * 128 + ((unit ^ (row & 7)) << 4));
                }
        }

        const int p3 = j % 3, kb = j * 64;
        if (kb <= wrow + 31) {   // warp not fully masked
            // ---- S = Q K^T  (K fragments shared across both row-blocks)
            const uint32_t Kb = sb + FK_OFF + p3 * 8192;
            float s[8][2][4];
            #pragma unroll
            for (int t = 0; t < 8; t++)
                #pragma unroll
                for (int rb = 0; rb < 2; rb++)
                    #pragma unroll
                    for (int r = 0; r < 4; r++) s[t][rb][r] = 0.f;
            #pragma unroll
            for (int t = 0; t < 8; t++) {
                uint32_t bfr[8];
                #pragma unroll
                for (int kp = 0; kp < 2; kp++) {
                    int row = 8 * t + r8;
                    int unit = 4 * kp + g8;
                    LDSM4(bfr[4 * kp], bfr[4 * kp + 1], bfr[4 * kp + 2], bfr[4 * kp + 3],
                          Kb + row * 128 + ((unit ^ (row & 7)) << 4));
                }
                #pragma unroll
                for (int ks = 0; ks < 4; ks++)
                    #pragma unroll
                    for (int rb = 0; rb < 2; rb++)
                        mma_f16(s[t][rb], qa[ks][rb], &bfr[2 * ks]);
            }
            // ---- mask + row max (4 groups: rb*2 + half)
            float tm[4] = {-1e30f, -1e30f, -1e30f, -1e30f};
            if (kb + 63 < wrow) {   // warp-uniform fully-unmasked tile
                #pragma unroll
                for (int t = 0; t < 8; t++)
                    #pragma unroll
                    for (int rb = 0; rb < 2; rb++) {
                        tm[2 * rb]     = fmaxf(tm[2 * rb], fmaxf(s[t][rb][0], s[t][rb][1]));
                        tm[2 * rb + 1] = fmaxf(tm[2 * rb + 1], fmaxf(s[t][rb][2], s[t][rb][3]));
                    }
            } else {
                #pragma unroll
                for (int t = 0; t < 8; t++) {
                    const int c0 = kb + 8 * t + 2 * gc, c1 = c0 + 1;
                    #pragma unroll
                    for (int rb = 0; rb < 2; rb++) {
                        const int rlo = wrow + rb * 16 + gr, rhi = rlo + 8;
                        s[t][rb][0] = (c0 <= rlo) ? s[t][rb][0] : MASKF;
                        s[t][rb][1] = (c1 <= rlo) ? s[t][rb][1] : MASKF;
                        s[t][rb][2] = (c0 <= rhi) ? s[t][rb][2] : MASKF;
                        s[t][rb][3] = (c1 <= rhi) ? s[t][rb][3] : MASKF;
                        tm[2 * rb]     = fmaxf(tm[2 * rb], fmaxf(s[t][rb][0], s[t][rb][1]));
                        tm[2 * rb + 1] = fmaxf(tm[2 * rb + 1], fmaxf(s[t][rb][2], s[t][rb][3]));
                    }
                }
            }
            #pragma unroll
            for (int k = 0; k < 4; k++)
                #pragma unroll
                for (int off = 1; off <= 2; off <<= 1)
                    tm[k] = fmaxf(tm[k], __shfl_xor_sync(0xffffffffu, tm[k], off));
            float mn[4], cf[4];
            #pragma unroll
            for (int k = 0; k < 4; k++) {
                mn[k] = fmaxf(m[k], tm[k]);
                cf[k] = ex2f(m[k] - mn[k]);
                m[k] = mn[k];
            }
            // ---- P = ex2(s - m) in fp16 pairs
            uint32_t pa[4][2][4];
            #pragma unroll
            for (int t = 0; t < 8; t++) {
                const int ks = t >> 1, hi = (t & 1) * 2;
                #pragma unroll
                for (int rb = 0; rb < 2; rb++) {
                    pa[ks][rb][hi]     = ex2_h2(pack_h2(s[t][rb][0] - mn[2 * rb],
                                                        s[t][rb][1] - mn[2 * rb]));
                    pa[ks][rb][hi + 1] = ex2_h2(pack_h2(s[t][rb][2] - mn[2 * rb + 1],
                                                        s[t][rb][3] - mn[2 * rb + 1]));
                }
            }
            #pragma unroll
            for (int rb = 0; rb < 2; rb++) {
                lrow[rb][0] *= cf[2 * rb];     lrow[rb][1] *= cf[2 * rb];
                lrow[rb][2] *= cf[2 * rb + 1]; lrow[rb][3] *= cf[2 * rb + 1];
                #pragma unroll
                for (int t = 0; t < 8; t++) {
                    o[rb][t][0] *= cf[2 * rb];     o[rb][t][1] *= cf[2 * rb];
                    o[rb][t][2] *= cf[2 * rb + 1]; o[rb][t][3] *= cf[2 * rb + 1];
                }
            }
            // ---- l += P @ ones
            #pragma unroll
            for (int ks = 0; ks < 4; ks++)
                #pragma unroll
                for (int rb = 0; rb < 2; rb++)
                    mma_f16(lrow[rb], pa[ks][rb], onesb);
            // ---- O += P V  (V fragments shared across both row-blocks)
            const uint32_t Vb = sb + FV_OFF + p3 * 8192;
            #pragma unroll
            for (int tp = 0; tp < 4; tp++) {
                #pragma unroll
                for (int ks = 0; ks < 4; ks++) {
                    uint32_t bv[4];
                    int row = 16 * ks + (g8 & 1) * 8 + r8;
                    int unit = 2 * tp + (g8 >> 1);
                    LDSM4T(bv[0], bv[1], bv[2], bv[3],
                           Vb + row * 128 + ((unit ^ (row & 7)) << 4));
                    #pragma unroll
                    for (int rb = 0; rb < 2; rb++) {
                        mma_f16(o[rb][2 * tp], pa[ks][rb], &bv[0]);
                        mma_f16(o[rb][2 * tp + 1], pa[ks][rb], &bv[2]);
                    }
                }
            }
        }
    }

    #pragma unroll
    for (int rb = 0; rb < 2; rb++) {
        const float i0 = 1.f / lrow[rb][0], i1 = 1.f / lrow[rb][2];
        const int rlo = q0 + wid * 32 + rb * 16 + gr;
        __half* y0 = y + (size_t)(b * SEQ + rlo) * N_EMBD + h * HS;
        __half* y1 = y + (size_t)(b * SEQ + rlo + 8) * N_EMBD + h * HS;
        #pragma unroll
        for (int t = 0; t < 8; t++) {
            *(__half2*)(y0 + 8 * t + 2 * gc) =
                __floats2half2_rn(o[rb][t][0] * i0, o[rb][t][1] * i0);
            *(__half2*)(y1 + 8 * t + 2 * gc) =
                __floats2half2_rn(o[rb][t][2] * i1, o[rb][t][3] * i1);
        }
    }
}

// ---------------------------------------------------------------------------
extern "C" void kernel_launch(void* const* d_in, const int* in_sizes, int n_in,
                              void* d_out, int out_size)
{
    const float* x      = (const float*)d_in[0];
    const float* w_attn = (const float*)d_in[1];
    const float* w_proj = (const float*)d_in[2];
    float* out = (float*)d_out;

    __half *xh, *qkvh, *yh, *wta, *wtp;
    cudaGetSymbolAddress((void**)&xh, g_xh);
    cudaGetSymbolAddress((void**)&qkvh, g_qkvh);
    cudaGetSymbolAddress((void**)&yh, g_yh);
    cudaGetSymbolAddress((void**)&wta, g_wta_h);
    cudaGetSymbolAddress((void**)&wtp, g_wtp_h);

    cudaFuncSetAttribute(gemm_f16<true>, cudaFuncAttributeMaxDynamicSharedMemorySize, GEMM_SMEM);
    cudaFuncSetAttribute(gemm_f16<false>, cudaFuncAttributeMaxDynamicSharedMemorySize, GEMM_SMEM);
    cudaFuncSetAttribute(flash_f16, cudaFuncAttributeMaxDynamicSharedMemorySize, FLASH_SMEM);

    const int n4 = MTOT * N_EMBD / 4;
    cvt_half4<<<n4 / 256, 256>>>((const float4*)x, (__half2*)xh, n4);
    transpose_cvt<<<dim3(3 * N_EMBD / 32, N_EMBD / 32), 256>>>(w_attn, wta, N_EMBD, 3 * N_EMBD);
    transpose_cvt<<<dim3(N_EMBD / 32, N_EMBD / 32), 256>>>(w_proj, wtp, N_EMBD, N_EMBD);

    gemm_f16<true><<<dim3(3 * N_EMBD / 128, MTOT / 128), 256, GEMM_SMEM>>>(
        xh, wta, qkvh, MTOT, 3 * N_EMBD, N_EMBD, 1);

    flash_f16<<<dim3(SEQ / 128, BATCH * N_HEAD), 128, FLASH_SMEM>>>(qkvh, yh);

    gemm_f16<false><<<dim3(N_EMBD / 128, MTOT / 128), 256, GEMM_SMEM>>>(
        yh, wtp, out, MTOT, N_EMBD, N_EMBD, 0);
}